// round 5
// baseline (speedup 1.0000x reference)
#include <cuda_runtime.h>
#include <math.h>

// Problem shape (fixed): B=256, T=1024, H=128, FUTURE=32.
#define BB    256
#define HH    128
#define KK1   129          // cell1 input  [x, h1_prev]
#define KK2   257          // cell2 input  [x, h1_new, h2_prev]
#define KK3   385          // cell3 input  [x, h1_new, h2_new, h3_prev]
#define GRIDN 128          // persistent CTAs, 1/SM, co-resident
#define NTHR  128          // 4 warps; warp = 2 hidden rows x 32 batch cols

// ---------------- device-global exchange state (allocation-free) -------------
__device__ float g_h1[HH * BB];
__device__ float g_h2[HH * BB];
__device__ float g_h3[HH * BB];
__device__ unsigned g_arr;
__device__ unsigned g_gen;

__global__ void lstm_bar_init() { g_arr = 0u; g_gen = 0u; }

// ---------------- grid-wide generation barrier -------------------------------
__device__ __forceinline__ void gsync(unsigned &lg) {
    __syncthreads();
    if (threadIdx.x == 0) {
        unsigned target = lg + 1u;
        __threadfence();                       // release: h stores -> L2
        unsigned old = atomicAdd(&g_arr, 1u);
        if (old == GRIDN - 1u) {
            atomicExch(&g_arr, 0u);
            __threadfence();
            atomicExch(&g_gen, target);
        } else {
            volatile unsigned *p = &g_gen;
            while (*p < target) { }
        }
        __threadfence();                       // acquire
        lg = target;
    }
    __syncthreads();
}

// ---------------- packed f32x2 FMA (Blackwell dual-FP32 path) ----------------
__device__ __forceinline__ void ffma2(unsigned long long &d,
                                      unsigned long long a,
                                      unsigned long long b) {
    asm("fma.rn.f32x2 %0, %1, %2, %0;" : "+l"(d) : "l"(a), "l"(b));
}
__device__ __forceinline__ float f2lo(unsigned long long v) {
    return __uint_as_float((unsigned)v);
}
__device__ __forceinline__ float f2hi(unsigned long long v) {
    return __uint_as_float((unsigned)(v >> 32));
}

// ---------------- activations ------------------------------------------------
__device__ __forceinline__ float sigf(float v) {
    return __fdividef(1.0f, 1.0f + __expf(-v));
}
__device__ __forceinline__ float tanhfast(float v) {
    return 2.0f * sigf(2.0f * v) - 1.0f;
}

// ---------------- one LSTM cell: thread handles 2 rows x 1 col, 4 gates ------
// wsf   : [K][rp(4)][g(4)][row-pair(2)] floats  (pre-paired rows)
// biasc : same pairing, 32 floats for this cell
// big2  : [K][col(32)][2 duplicated] floats     (v splat ready for LDS.64)
template <int K>
__device__ __forceinline__ void cell_eval2(const float *__restrict__ wsf,
                                           const float *__restrict__ biasc,
                                           const float *__restrict__ big2,
                                           int lane, int rp,
                                           float &ca, float &cb,
                                           float &ha, float &hb) {
    const ulonglong2 *wp = (const ulonglong2 *)wsf + rp * 2;  // 16B units
    const unsigned long long *vp = (const unsigned long long *)big2 + lane;
    const ulonglong2 *bp = (const ulonglong2 *)biasc + rp * 2;
    ulonglong2 b01 = bp[0], b23 = bp[1];
    unsigned long long a0 = b01.x, a1 = b01.y, a2 = b23.x, a3 = b23.y;
#pragma unroll 4
    for (int k = 0; k < K; k++) {
        ulonglong2 w01 = wp[k * 8];       // gates i,f  (2 rows each)
        ulonglong2 w23 = wp[k * 8 + 1];   // gates g,o
        unsigned long long v = vp[k * 32];
        ffma2(a0, w01.x, v);
        ffma2(a1, w01.y, v);
        ffma2(a2, w23.x, v);
        ffma2(a3, w23.y, v);
    }
    float ia = sigf(f2lo(a0)), ib = sigf(f2hi(a0));
    float fa = sigf(f2lo(a1)), fb = sigf(f2hi(a1));
    float ga = tanhfast(f2lo(a2)), gb = tanhfast(f2hi(a2));
    float oa = sigf(f2lo(a3)), ob = sigf(f2hi(a3));
    ca = fa * ca + ia * ga;
    cb = fb * cb + ib * gb;
    ha = oa * tanhfast(ca);
    hb = ob * tanhfast(cb);
}

// ---------------- smem layout (floats) ---------------------------------------
#define WS1_F   (KK1 * 32)          // 4128
#define WS2_F   (KK2 * 32)          // 8224
#define WS3_F   (KK3 * 32)          // 12320
#define BIAS_F  96
#define WL_F    392
#define BIG2_F  (KK3 * 64)          // 24640 (duplicated inputs)
#define PO_F    128
#define OX_F    32
#define SMEM_FLOATS (WS1_F + WS2_F + WS3_F + BIAS_F + WL_F + BIG2_F + PO_F + OX_F)
#define SMEM_BYTES  (SMEM_FLOATS * 4)

__global__ void __launch_bounds__(NTHR, 1)
lstm_persist_kernel(const float *__restrict__ x,
                    const float *__restrict__ Wi1, const float *__restrict__ Wh1,
                    const float *__restrict__ bi1, const float *__restrict__ bh1,
                    const float *__restrict__ Wi2, const float *__restrict__ Wh2,
                    const float *__restrict__ bi2, const float *__restrict__ bh2,
                    const float *__restrict__ Wi3, const float *__restrict__ Wh3,
                    const float *__restrict__ bi3, const float *__restrict__ bh3,
                    const float *__restrict__ Wl,  const float *__restrict__ bl,
                    float *__restrict__ out, int T, int NT) {
    extern __shared__ float sm[];
    float *ws1f  = sm;
    float *ws2f  = ws1f + WS1_F;
    float *ws3f  = ws2f + WS2_F;
    float *biasf = ws3f + WS3_F;
    float *wl    = biasf + BIAS_F;
    float *big2  = wl + WL_F;           // 16B aligned (offset 25160 floats)
    float *po_s  = big2 + BIG2_F;
    float *ox    = po_s + PO_F;

    const int tid  = threadIdx.x;
    const int lane = tid & 31;          // batch col within group
    const int rp   = tid >> 5;          // warp id == local row-pair (rows 2rp,2rp+1)
    const int hg   = blockIdx.x & 15;   // hidden group (16 x 8 rows)
    const int bg   = blockIdx.x >> 4;   // batch group (8 x 32 cols)
    const int bcol = bg * 32 + lane;
    unsigned lg = 0;

    // ---- stage per-CTA weight slices once; layout [k][rp][g][rr] ------------
    // idx bits: k = idx>>5 ; t5 = idx&31 : rp'=t5>>3, g=(t5>>1)&3, rr=t5&1
    for (int idx = tid; idx < WS1_F; idx += NTHR) {
        int k = idx >> 5, t5 = idx & 31;
        int g = (t5 >> 1) & 3, rr = t5 & 1, rpp = t5 >> 3;
        int row = g * HH + hg * 8 + rpp * 2 + rr;
        ws1f[idx] = (k == 0) ? Wi1[row] : Wh1[row * HH + (k - 1)];
    }
    for (int idx = tid; idx < WS2_F; idx += NTHR) {
        int k = idx >> 5, t5 = idx & 31;
        int g = (t5 >> 1) & 3, rr = t5 & 1, rpp = t5 >> 3;
        int row = g * HH + hg * 8 + rpp * 2 + rr;
        ws2f[idx] = (k < KK1) ? Wi2[row * KK1 + k] : Wh2[row * HH + (k - KK1)];
    }
    for (int idx = tid; idx < WS3_F; idx += NTHR) {
        int k = idx >> 5, t5 = idx & 31;
        int g = (t5 >> 1) & 3, rr = t5 & 1, rpp = t5 >> 3;
        int row = g * HH + hg * 8 + rpp * 2 + rr;
        ws3f[idx] = (k < 257) ? Wi3[row * 257 + k] : Wh3[row * HH + (k - 257)];
    }
    if (tid < 96) {
        int cell = tid >> 5, t5 = tid & 31;
        int g = (t5 >> 1) & 3, rr = t5 & 1, rpp = t5 >> 3;
        int row = g * HH + hg * 8 + rpp * 2 + rr;
        float b;
        if (cell == 0)      b = bi1[row] + bh1[row];
        else if (cell == 1) b = bi2[row] + bh2[row];
        else                b = bi3[row] + bh3[row];
        biasf[cell * 32 + t5] = b;
    }
    for (int idx = tid; idx < 385; idx += NTHR) wl[idx] = Wl[idx];
    if (tid == 0) wl[385] = bl[0];
    if (tid < 32) ox[tid] = 0.0f;

    // zero big2: h slots hold h_prev = 0 at t=0 (buffer carries state onward)
    for (int idx = tid; idx < KK3 * 32; idx += NTHR)
        ((float2 *)big2)[idx] = make_float2(0.0f, 0.0f);
    __syncthreads();

    float c1a = 0.f, c1b = 0.f, c2a = 0.f, c2b = 0.f, c3a = 0.f, c3b = 0.f;
    const int rbase = (hg * 8 + rp * 2) * BB + bcol;

    for (int t = 0; t < NT; t++) {
        // ---- refresh x slot only; h slots already hold h_prev ---------------
        if (tid < 32) {
            float xv = (t < T) ? __ldg(&x[(bg * 32 + tid) * T + t]) : ox[tid];
            ((float2 *)big2)[tid] = make_float2(xv, xv);
        }
        __syncthreads();

        // ---- cell 1 ---------------------------------------------------------
        float h1a, h1b;
        cell_eval2<KK1>(ws1f, biasf + 0, big2, lane, rp, c1a, c1b, h1a, h1b);
        g_h1[rbase] = h1a;
        g_h1[rbase + BB] = h1b;
        gsync(lg);
        {   // stage h1_new -> slots 1..128 (duplicated)
            const float *s = &g_h1[bg * 32];
            float2 *d = (float2 *)big2 + 32;
            for (int idx = tid; idx < HH * 32; idx += NTHR) {
                float v = __ldcg(s + (idx >> 5) * BB + (idx & 31));
                d[idx] = make_float2(v, v);
            }
        }
        __syncthreads();

        // ---- cell 2 ---------------------------------------------------------
        float h2a, h2b;
        cell_eval2<KK2>(ws2f, biasf + 32, big2, lane, rp, c2a, c2b, h2a, h2b);
        g_h2[rbase] = h2a;
        g_h2[rbase + BB] = h2b;
        gsync(lg);
        {   // stage h2_new -> slots 129..256
            const float *s = &g_h2[bg * 32];
            float2 *d = (float2 *)big2 + 129 * 32;
            for (int idx = tid; idx < HH * 32; idx += NTHR) {
                float v = __ldcg(s + (idx >> 5) * BB + (idx & 31));
                d[idx] = make_float2(v, v);
            }
        }
        __syncthreads();

        // ---- cell 3 ---------------------------------------------------------
        float h3a, h3b;
        cell_eval2<KK3>(ws3f, biasf + 64, big2, lane, rp, c3a, c3b, h3a, h3b);
        g_h3[rbase] = h3a;
        g_h3[rbase + BB] = h3b;
        gsync(lg);
        {   // stage h3_new -> slots 257..384
            const float *s = &g_h3[bg * 32];
            float2 *d = (float2 *)big2 + 257 * 32;
            for (int idx = tid; idx < HH * 32; idx += NTHR) {
                float v = __ldcg(s + (idx >> 5) * BB + (idx & 31));
                d[idx] = make_float2(v, v);
            }
        }
        __syncthreads();

        // ---- linear head: o_t = [x,h1,h2,h3].Wl + b (per CTA, own cols) -----
        {
            const int sub = tid >> 5;   // 0..3
            float p = 0.0f;
            for (int k = sub; k < 385; k += 4)
                p = fmaf(wl[k], big2[k * 64 + lane * 2], p);
            po_s[sub * 32 + lane] = p;
            __syncthreads();
            if (tid < 32) {
                float o = wl[385] + po_s[tid] + po_s[32 + tid] +
                          po_s[64 + tid] + po_s[96 + tid];
                ox[tid] = o;                                     // feedback x_{t+1}
                if (hg == 0) out[(bg * 32 + tid) * NT + t] = o;  // one writer group
            }
            __syncthreads();
        }
    }
}

extern "C" void kernel_launch(void* const* d_in, const int* in_sizes, int n_in,
                              void* d_out, int out_size) {
    const float *x   = (const float *)d_in[0];
    const float *Wi1 = (const float *)d_in[1];
    const float *Wh1 = (const float *)d_in[2];
    const float *bi1 = (const float *)d_in[3];
    const float *bh1 = (const float *)d_in[4];
    const float *Wi2 = (const float *)d_in[5];
    const float *Wh2 = (const float *)d_in[6];
    const float *bi2 = (const float *)d_in[7];
    const float *bh2 = (const float *)d_in[8];
    const float *Wi3 = (const float *)d_in[9];
    const float *Wh3 = (const float *)d_in[10];
    const float *bi3 = (const float *)d_in[11];
    const float *bh3 = (const float *)d_in[12];
    const float *Wl  = (const float *)d_in[13];
    const float *bl  = (const float *)d_in[14];
    float *out = (float *)d_out;

    int T  = in_sizes[0] / BB;   // 1024
    int NT = out_size / BB;      // 1056

    cudaFuncSetAttribute(lstm_persist_kernel,
                         cudaFuncAttributeMaxDynamicSharedMemorySize, SMEM_BYTES);

    lstm_bar_init<<<1, 1>>>();
    lstm_persist_kernel<<<GRIDN, NTHR, SMEM_BYTES>>>(
        x, Wi1, Wh1, bi1, bh1, Wi2, Wh2, bi2, bh2,
        Wi3, Wh3, bi3, bh3, Wl, bl, out, T, NT);
}

// round 6
// speedup vs baseline: 1.2847x; 1.2847x over previous
#include <cuda_runtime.h>
#include <math.h>

// Problem shape (fixed): B=256, T=1024, H=128, FUTURE=32.
#define BB    256
#define HH    128
#define KK1   129          // cell1 input  [x, h1]
#define KK2   257          // cell2 input  [x, h1, h2]
#define KK3   385          // cell3 input  [x, h1, h2, h3]
#define GRIDN 128          // persistent CTAs, 1/SM, co-resident
#define NTHR  256          // 8 warps; warp = 1 hidden row, lanes = 32 batch cols

// ---------------- device-global exchange state (allocation-free) -------------
__device__ float g_h1[HH * BB];
__device__ float g_h2[HH * BB];
__device__ float g_h3[HH * BB];
__device__ unsigned g_flags[GRIDN * 32];    // one 128B line per CTA

__global__ void lstm_bar_init() {
    for (int i = threadIdx.x; i < GRIDN * 32; i += blockDim.x) g_flags[i] = 0u;
}

// ---------------- distributed flag barrier -----------------------------------
// arrive: call with all CTA threads past a __syncthreads that covers the h
// stores; tid 0 publishes the phase counter (release via threadfence).
__device__ __forceinline__ void bar_arrive(unsigned p, int tid) {
    if (tid == 0) {
        __threadfence();
        asm volatile("st.relaxed.gpu.u32 [%0], %1;"
                     :: "l"(&g_flags[blockIdx.x * 32]), "r"(p) : "memory");
    }
}
// wait: threads 0..127 poll one flag each (parallel across L2 lines), then
// acquire-fence and block-sync.
__device__ __forceinline__ void bar_wait(unsigned p, int tid) {
    if (tid < GRIDN) {
        unsigned v;
        do {
            asm volatile("ld.relaxed.gpu.u32 %0, [%1];"
                         : "=r"(v) : "l"(&g_flags[tid * 32]) : "memory");
        } while (v < p);
    }
    __threadfence();
    __syncthreads();
}

// ---------------- activations ------------------------------------------------
__device__ __forceinline__ float sigf(float v) {
    return __fdividef(1.0f, 1.0f + __expf(-v));
}
__device__ __forceinline__ float tanhfast(float v) {
    return 2.0f * sigf(2.0f * v) - 1.0f;
}

// ---------------- gate accumulation over a k-range ---------------------------
// wsq : [k][j(8)][g(4)] floats viewed as float4[k][8]
// in_s: [k][32] floats
template <int K0, int K1>
__device__ __forceinline__ float4 accum_range(const float4 *__restrict__ wsq,
                                              float4 acc,
                                              const float *__restrict__ in_s,
                                              int lane, int j) {
    const float4 *wp = wsq + j;
    const float  *ip = in_s + lane;
#pragma unroll 4
    for (int k = K0; k < K1; k++) {
        float4 w = wp[k * 8];              // LDS.128 lane-uniform broadcast
        float  v = ip[k * 32];             // conflict-free LDS.32
        acc.x = fmaf(w.x, v, acc.x);
        acc.y = fmaf(w.y, v, acc.y);
        acc.z = fmaf(w.z, v, acc.z);
        acc.w = fmaf(w.w, v, acc.w);
    }
    return acc;
}

__device__ __forceinline__ float lstm_out(float4 a, float &c) {
    float ig = sigf(a.x), fg = sigf(a.y);
    float gg = tanhfast(a.z), og = sigf(a.w);
    c = fg * c + ig * gg;
    return og * tanhfast(c);
}

// stage one h vector (this CTA's 32 cols, all 128 rows) L2 -> smem slot
__device__ __forceinline__ void stage_h(const float *__restrict__ src,
                                        float *__restrict__ dst, int tid) {
#pragma unroll
    for (int i = 0; i < (HH * 32) / NTHR; i++) {       // 16 iters
        int idx = tid + i * NTHR;
        dst[idx] = __ldcg(src + (idx >> 5) * BB + (idx & 31));
    }
}

// ---------------- smem layout (floats) ---------------------------------------
#define WS1_F   (KK1 * 32)          // 4128
#define WS2_F   (KK2 * 32)          // 8224
#define WS3_F   (KK3 * 32)          // 12320
#define BIAS_F  96
#define WL_F    392
#define BIG_F   (KK3 * 32)          // 12320 : persistent [x|h1|h2|h3] prefix buffer
#define PO_F    256
#define OX_F    32
#define SMEM_FLOATS (WS1_F + WS2_F + WS3_F + BIAS_F + WL_F + BIG_F + PO_F + OX_F)
#define SMEM_BYTES  (SMEM_FLOATS * 4)

__global__ void __launch_bounds__(NTHR, 1)
lstm_persist_kernel(const float *__restrict__ x,
                    const float *__restrict__ Wi1, const float *__restrict__ Wh1,
                    const float *__restrict__ bi1, const float *__restrict__ bh1,
                    const float *__restrict__ Wi2, const float *__restrict__ Wh2,
                    const float *__restrict__ bi2, const float *__restrict__ bh2,
                    const float *__restrict__ Wi3, const float *__restrict__ Wh3,
                    const float *__restrict__ bi3, const float *__restrict__ bh3,
                    const float *__restrict__ Wl,  const float *__restrict__ bl,
                    float *__restrict__ out, int T, int NT) {
    extern __shared__ float sm[];
    float *ws1f  = sm;
    float *ws2f  = ws1f + WS1_F;
    float *ws3f  = ws2f + WS2_F;
    float *biasf = ws3f + WS3_F;
    float *wl    = biasf + BIAS_F;
    float *big   = wl + WL_F;
    float *po_s  = big + BIG_F;
    float *ox    = po_s + PO_F;

    const float4 *ws1 = (const float4 *)ws1f;
    const float4 *ws2 = (const float4 *)ws2f;
    const float4 *ws3 = (const float4 *)ws3f;
    const float4 *bias4 = (const float4 *)biasf;

    const int tid  = threadIdx.x;
    const int lane = tid & 31;          // batch col within group
    const int j    = tid >> 5;          // warp id == local hidden row (0..7)
    const int hg   = blockIdx.x & 15;   // hidden group (16 x 8 rows)
    const int bg   = blockIdx.x >> 4;   // batch group (8 x 32 cols)
    const int bcol = bg * 32 + lane;
    const int row  = hg * 8 + j;        // global hidden row
    const int gidx = row * BB + bcol;

    // ---- stage per-CTA weight slices once (layout [k][j][gate]) -------------
    for (int idx = tid; idx < WS1_F; idx += NTHR) {
        int k = idx >> 5, t5 = idx & 31, jj = t5 >> 2, g = t5 & 3;
        int r = g * HH + hg * 8 + jj;
        ws1f[idx] = (k == 0) ? Wi1[r] : Wh1[r * HH + (k - 1)];
    }
    for (int idx = tid; idx < WS2_F; idx += NTHR) {
        int k = idx >> 5, t5 = idx & 31, jj = t5 >> 2, g = t5 & 3;
        int r = g * HH + hg * 8 + jj;
        ws2f[idx] = (k < KK1) ? Wi2[r * KK1 + k] : Wh2[r * HH + (k - KK1)];
    }
    for (int idx = tid; idx < WS3_F; idx += NTHR) {
        int k = idx >> 5, t5 = idx & 31, jj = t5 >> 2, g = t5 & 3;
        int r = g * HH + hg * 8 + jj;
        ws3f[idx] = (k < 257) ? Wi3[r * 257 + k] : Wh3[r * HH + (k - 257)];
    }
    if (tid < 96) {
        int cell = tid >> 5, t5 = tid & 31, jj = t5 >> 2, g = t5 & 3;
        int r = g * HH + hg * 8 + jj;
        float b;
        if (cell == 0)      b = bi1[r] + bh1[r];
        else if (cell == 1) b = bi2[r] + bh2[r];
        else                b = bi3[r] + bh3[r];
        biasf[cell * 32 + t5] = b;
    }
    for (int idx = tid; idx < 385; idx += NTHR) wl[idx] = Wl[idx];
    if (tid == 0) wl[385] = bl[0];
    if (tid < 32) ox[tid] = 0.0f;

    // big holds h_prev = 0 at t=0 (buffer carries state forward each step)
    for (int idx = tid; idx < BIG_F; idx += NTHR) big[idx] = 0.0f;
    __syncthreads();

    float c1 = 0.f, c2 = 0.f, c3 = 0.f;
    unsigned p = 0;

    for (int t = 0; t < NT; t++) {
        // ---- refresh x slot; h slots already hold h_prev --------------------
        if (tid < 32) {
            float xv = (t < T) ? __ldg(&x[(bg * 32 + tid) * T + t]) : ox[tid];
            big[tid] = xv;
        }
        __syncthreads();

        // ================= cell 1 (full: x + h1_prev) ========================
        float4 a1 = accum_range<0, KK1>(ws1, bias4[0 * 8 + j], big, lane, j);
        float h1 = lstm_out(a1, c1);
        g_h1[gidx] = h1;
        __syncthreads();
        p++; bar_arrive(p, tid);

        // overlap: cell2 partial over x (k=0) and h2_prev (k=129..257)
        float4 a2 = bias4[1 * 8 + j];
        a2 = accum_range<0, 1>(ws2, a2, big, lane, j);
        a2 = accum_range<129, 257>(ws2, a2, big, lane, j);

        bar_wait(p, tid);
        stage_h(&g_h1[bg * 32], big + 32, tid);          // h1_new -> slots 1..128
        __syncthreads();

        // ================= cell 2 (finish: h1_new) ===========================
        a2 = accum_range<1, 129>(ws2, a2, big, lane, j);
        float h2 = lstm_out(a2, c2);
        g_h2[gidx] = h2;
        __syncthreads();
        p++; bar_arrive(p, tid);

        // overlap: cell3 partial over x + h1_new (k=0..129) and h3_prev (257..385)
        float4 a3 = bias4[2 * 8 + j];
        a3 = accum_range<0, 129>(ws3, a3, big, lane, j);
        a3 = accum_range<257, 385>(ws3, a3, big, lane, j);

        bar_wait(p, tid);
        stage_h(&g_h2[bg * 32], big + 129 * 32, tid);    // h2_new -> slots 129..256
        __syncthreads();

        // ================= cell 3 (finish: h2_new) ===========================
        a3 = accum_range<129, 257>(ws3, a3, big, lane, j);
        float h3 = lstm_out(a3, c3);
        g_h3[gidx] = h3;
        __syncthreads();
        p++; bar_arrive(p, tid);

        // overlap: head partial over x,h1,h2 (k < 257)
        const int sub = j;               // 8 sub-slices
        float hp = 0.0f;
        int k = sub;
        for (; k < 257; k += 8) hp = fmaf(wl[k], big[k * 32 + lane], hp);

        bar_wait(p, tid);
        stage_h(&g_h3[bg * 32], big + 257 * 32, tid);    // h3_new -> slots 257..384
        __syncthreads();

        // ================= linear head finish + output =======================
        for (; k < 385; k += 8) hp = fmaf(wl[k], big[k * 32 + lane], hp);
        po_s[sub * 32 + lane] = hp;
        __syncthreads();
        if (tid < 32) {
            float o = wl[385];
#pragma unroll
            for (int s = 0; s < 8; s++) o += po_s[s * 32 + tid];
            ox[tid] = o;                                     // feedback x_{t+1}
            if (hg == 0) out[(bg * 32 + tid) * NT + t] = o;  // one writer group
        }
        __syncthreads();
    }
}

extern "C" void kernel_launch(void* const* d_in, const int* in_sizes, int n_in,
                              void* d_out, int out_size) {
    const float *x   = (const float *)d_in[0];
    const float *Wi1 = (const float *)d_in[1];
    const float *Wh1 = (const float *)d_in[2];
    const float *bi1 = (const float *)d_in[3];
    const float *bh1 = (const float *)d_in[4];
    const float *Wi2 = (const float *)d_in[5];
    const float *Wh2 = (const float *)d_in[6];
    const float *bi2 = (const float *)d_in[7];
    const float *bh2 = (const float *)d_in[8];
    const float *Wi3 = (const float *)d_in[9];
    const float *Wh3 = (const float *)d_in[10];
    const float *bi3 = (const float *)d_in[11];
    const float *bh3 = (const float *)d_in[12];
    const float *Wl  = (const float *)d_in[13];
    const float *bl  = (const float *)d_in[14];
    float *out = (float *)d_out;

    int T  = in_sizes[0] / BB;   // 1024
    int NT = out_size / BB;      // 1056

    cudaFuncSetAttribute(lstm_persist_kernel,
                         cudaFuncAttributeMaxDynamicSharedMemorySize, SMEM_BYTES);

    lstm_bar_init<<<1, 256>>>();
    lstm_persist_kernel<<<GRIDN, NTHR, SMEM_BYTES>>>(
        x, Wi1, Wh1, bi1, bh1, Wi2, Wh2, bi2, bh2,
        Wi3, Wh3, bi3, bh3, Wl, bl, out, T, NT);
}

// round 7
// speedup vs baseline: 1.3930x; 1.0843x over previous
#include <cuda_runtime.h>
#include <math.h>

// Problem shape (fixed): B=256, T=1024, H=128, FUTURE=32.
#define BB    256
#define HH    128
#define KK1   129          // cell1 input  [x, h1]
#define KK2   257          // cell2 input  [x, h1, h2]
#define KK3   385          // cell3 input  [x, h1, h2, h3]
#define GRIDN 128          // persistent CTAs, 1/SM, co-resident
#define NTHR  256          // 8 warps; warp = 1 hidden row, lanes = 32 batch cols

// ---------------- device-global exchange state (allocation-free) -------------
__device__ __align__(16) float g_h1[HH * BB];
__device__ __align__(16) float g_h2[HH * BB];
__device__ __align__(16) float g_h3[2][HH * BB];   // double buffer (deferred read)
__device__ unsigned g_flags[GRIDN * 32];           // one 128B line per CTA

__global__ void lstm_bar_init() {
    for (int i = threadIdx.x; i < GRIDN * 32; i += blockDim.x) g_flags[i] = 0u;
}

// ---------------- distributed flag barrier -----------------------------------
__device__ __forceinline__ void bar_arrive(unsigned p, int tid) {
    if (tid == 0) {
        __threadfence();
        asm volatile("st.relaxed.gpu.u32 [%0], %1;"
                     :: "l"(&g_flags[blockIdx.x * 32]), "r"(p) : "memory");
    }
}
__device__ __forceinline__ void bar_wait(unsigned p, int tid) {
    if (tid < GRIDN) {
        unsigned v;
        do {
            asm volatile("ld.relaxed.gpu.u32 %0, [%1];"
                         : "=r"(v) : "l"(&g_flags[tid * 32]) : "memory");
        } while (v < p);
    }
    __threadfence();
    __syncthreads();
}

// ---------------- activations (HW tanh) --------------------------------------
__device__ __forceinline__ float tanha(float x) {
    float r; asm("tanh.approx.f32 %0, %1;" : "=f"(r) : "f"(x)); return r;
}
__device__ __forceinline__ float sigf(float v) {
    return fmaf(0.5f, tanha(0.5f * v), 0.5f);
}

// ---------------- gate accumulation over a k-range ---------------------------
template <int K0, int K1>
__device__ __forceinline__ float4 accum_range(const float4 *__restrict__ wsq,
                                              float4 acc,
                                              const float *__restrict__ in_s,
                                              int lane, int j) {
    const float4 *wp = wsq + j;
    const float  *ip = in_s + lane;
#pragma unroll 4
    for (int k = K0; k < K1; k++) {
        float4 w = wp[k * 8];              // LDS.128 lane-uniform broadcast
        float  v = ip[k * 32];             // conflict-free LDS.32
        acc.x = fmaf(w.x, v, acc.x);
        acc.y = fmaf(w.y, v, acc.y);
        acc.z = fmaf(w.z, v, acc.z);
        acc.w = fmaf(w.w, v, acc.w);
    }
    return acc;
}

__device__ __forceinline__ float lstm_out(float4 a, float &c) {
    float ig = sigf(a.x), fg = sigf(a.y);
    float gg = tanha(a.z), og = sigf(a.w);
    c = fg * c + ig * gg;
    return og * tanha(c);
}

// stage one h vector (this CTA's 32 cols, all 128 rows) L2 -> smem, vectorized
__device__ __forceinline__ void stage_h4(const float4 *__restrict__ src4,
                                         float4 *__restrict__ dst4, int tid) {
#pragma unroll
    for (int i = 0; i < 4; i++) {
        int idx = tid + i * NTHR;          // 0..1023
        int row = idx >> 3, q = idx & 7;
        dst4[row * 8 + q] = __ldcg(src4 + row * 64 + q);   // row stride 256 floats
    }
}

// ---------------- smem layout (floats) ---------------------------------------
#define WS1_F   (KK1 * 32)
#define WS2_F   (KK2 * 32)
#define WS3_F   (KK3 * 32)
#define BIAS_F  96
#define WL_F    392
#define BIG_F   (KK3 * 32)          // persistent [x|h1|h2|h3] prefix buffer
#define PO_F    256
#define OX_F    32
#define SMEM_FLOATS (WS1_F + WS2_F + WS3_F + BIAS_F + WL_F + BIG_F + PO_F + OX_F)
#define SMEM_BYTES  (SMEM_FLOATS * 4)

__global__ void __launch_bounds__(NTHR, 1)
lstm_persist_kernel(const float *__restrict__ x,
                    const float *__restrict__ Wi1, const float *__restrict__ Wh1,
                    const float *__restrict__ bi1, const float *__restrict__ bh1,
                    const float *__restrict__ Wi2, const float *__restrict__ Wh2,
                    const float *__restrict__ bi2, const float *__restrict__ bh2,
                    const float *__restrict__ Wi3, const float *__restrict__ Wh3,
                    const float *__restrict__ bi3, const float *__restrict__ bh3,
                    const float *__restrict__ Wl,  const float *__restrict__ bl,
                    float *__restrict__ out, int T, int NT) {
    extern __shared__ float sm[];
    float *ws1f  = sm;
    float *ws2f  = ws1f + WS1_F;
    float *ws3f  = ws2f + WS2_F;
    float *biasf = ws3f + WS3_F;
    float *wl    = biasf + BIAS_F;
    float *big   = wl + WL_F;
    float *po_s  = big + BIG_F;
    float *ox    = po_s + PO_F;

    const float4 *ws1 = (const float4 *)ws1f;
    const float4 *ws2 = (const float4 *)ws2f;
    const float4 *ws3 = (const float4 *)ws3f;
    const float4 *bias4 = (const float4 *)biasf;

    const int tid  = threadIdx.x;
    const int lane = tid & 31;
    const int j    = tid >> 5;          // warp id == local hidden row (0..7)
    const int hg   = blockIdx.x & 15;   // hidden group (16 x 8 rows)
    const int bg   = blockIdx.x >> 4;   // batch group (8 x 32 cols)
    const int bcol = bg * 32 + lane;
    const int row  = hg * 8 + j;
    const int gidx = row * BB + bcol;
    const int sub  = j;

    // ---- stage per-CTA weight slices once (layout [k][j][gate]) -------------
    for (int idx = tid; idx < WS1_F; idx += NTHR) {
        int k = idx >> 5, t5 = idx & 31, jj = t5 >> 2, g = t5 & 3;
        int r = g * HH + hg * 8 + jj;
        ws1f[idx] = (k == 0) ? Wi1[r] : Wh1[r * HH + (k - 1)];
    }
    for (int idx = tid; idx < WS2_F; idx += NTHR) {
        int k = idx >> 5, t5 = idx & 31, jj = t5 >> 2, g = t5 & 3;
        int r = g * HH + hg * 8 + jj;
        ws2f[idx] = (k < KK1) ? Wi2[r * KK1 + k] : Wh2[r * HH + (k - KK1)];
    }
    for (int idx = tid; idx < WS3_F; idx += NTHR) {
        int k = idx >> 5, t5 = idx & 31, jj = t5 >> 2, g = t5 & 3;
        int r = g * HH + hg * 8 + jj;
        ws3f[idx] = (k < 257) ? Wi3[r * 257 + k] : Wh3[r * HH + (k - 257)];
    }
    if (tid < 96) {
        int cell = tid >> 5, t5 = tid & 31, jj = t5 >> 2, g = t5 & 3;
        int r = g * HH + hg * 8 + jj;
        float b;
        if (cell == 0)      b = bi1[r] + bh1[r];
        else if (cell == 1) b = bi2[r] + bh2[r];
        else                b = bi3[r] + bh3[r];
        biasf[cell * 32 + t5] = b;
    }
    for (int idx = tid; idx < 385; idx += NTHR) wl[idx] = Wl[idx];
    if (tid == 0) wl[385] = bl[0];
    if (tid < 32) ox[tid] = 0.0f;
    for (int idx = tid; idx < BIG_F; idx += NTHR) big[idx] = 0.0f;
    __syncthreads();

    float c1 = 0.f, c2 = 0.f, c3 = 0.f;
    float hp = 0.f;                      // carried head partial (x,h1,h2 of t-1)
    unsigned p = 0;

    float xr = 0.f;
    if (tid < 32) xr = __ldg(&x[(bg * 32 + tid) * T]);   // prefetch x(0)

    for (int t = 0; t < NT; t++) {
        // ---- deferred head of t-1 at TOP only when x(t) needs o(t-1) --------
        if (t > 0 && t >= T) {
            bar_wait(3u * (unsigned)t, tid);                   // wait3(t-1)
            stage_h4((const float4 *)&g_h3[(t - 1) & 1][bg * 32],
                     (float4 *)(big + 257 * 32), tid);
            __syncthreads();
            for (int k = 257 + sub; k < 385; k += 8)
                hp = fmaf(wl[k], big[k * 32 + lane], hp);
            po_s[sub * 32 + lane] = hp;
            __syncthreads();
            if (tid < 32) {
                float o = wl[385];
#pragma unroll
                for (int s = 0; s < 8; s++) o += po_s[s * 32 + tid];
                ox[tid] = o;
                if (hg == 0) out[(bg * 32 + tid) * NT + (t - 1)] = o;
            }
            __syncthreads();
        }

        // ---- x slot (h slots already hold h_prev) ---------------------------
        if (tid < 32) big[tid] = (t < T) ? xr : ox[tid];
        __syncthreads();

        // ================= cell 1 (full: x + h1_prev) ========================
        float4 a1 = accum_range<0, KK1>(ws1, bias4[0 * 8 + j], big, lane, j);
        float h1 = lstm_out(a1, c1);
        g_h1[gidx] = h1;
        __syncthreads();
        p++; bar_arrive(p, tid);

        if (tid < 32 && t + 1 < T) xr = __ldg(&x[(bg * 32 + tid) * T + t + 1]);

        // overlap: cell2 partial over x (k=0) and h2_prev (k=129..257)
        float4 a2 = bias4[1 * 8 + j];
        a2 = accum_range<0, 1>(ws2, a2, big, lane, j);
        a2 = accum_range<129, 257>(ws2, a2, big, lane, j);

        bar_wait(p, tid);
        stage_h4((const float4 *)&g_h1[bg * 32], (float4 *)(big + 32), tid);
        __syncthreads();

        // ================= cell 2 (finish: h1_new) ===========================
        a2 = accum_range<1, 129>(ws2, a2, big, lane, j);
        float h2 = lstm_out(a2, c2);
        g_h2[gidx] = h2;
        __syncthreads();
        p++; bar_arrive(p, tid);

        // ---- deferred head of t-1 (main path: wait3 is a guaranteed no-op) --
        if (t > 0 && t < T) {
            bar_wait(3u * (unsigned)t, tid);                   // already satisfied
            stage_h4((const float4 *)&g_h3[(t - 1) & 1][bg * 32],
                     (float4 *)(big + 257 * 32), tid);
            __syncthreads();
            for (int k = 257 + sub; k < 385; k += 8)
                hp = fmaf(wl[k], big[k * 32 + lane], hp);
            po_s[sub * 32 + lane] = hp;
            __syncthreads();
            if (tid < 32) {
                float o = wl[385];
#pragma unroll
                for (int s = 0; s < 8; s++) o += po_s[s * 32 + tid];
                ox[tid] = o;
                if (hg == 0) out[(bg * 32 + tid) * NT + (t - 1)] = o;
            }
            __syncthreads();
        }

        // overlap: cell3 partial over x + h1_new (k=0..129) and h3_prev (257..385)
        float4 a3 = bias4[2 * 8 + j];
        a3 = accum_range<0, 129>(ws3, a3, big, lane, j);
        a3 = accum_range<257, 385>(ws3, a3, big, lane, j);

        bar_wait(p, tid);
        stage_h4((const float4 *)&g_h2[bg * 32], (float4 *)(big + 129 * 32), tid);
        __syncthreads();

        // ================= cell 3 (finish: h2_new) ===========================
        a3 = accum_range<129, 257>(ws3, a3, big, lane, j);
        float h3 = lstm_out(a3, c3);
        g_h3[t & 1][gidx] = h3;
        __syncthreads();
        p++; bar_arrive(p, tid);

        // head partial over x,h1,h2 of step t (carried to next iteration)
        hp = 0.0f;
        for (int k = sub; k < 257; k += 8)
            hp = fmaf(wl[k], big[k * 32 + lane], hp);
    }

    // ---- epilogue: deferred head of the last step ---------------------------
    {
        int tprev = NT - 1;
        bar_wait(3u * (unsigned)NT, tid);
        stage_h4((const float4 *)&g_h3[tprev & 1][bg * 32],
                 (float4 *)(big + 257 * 32), tid);
        __syncthreads();
        for (int k = 257 + sub; k < 385; k += 8)
            hp = fmaf(wl[k], big[k * 32 + lane], hp);
        po_s[sub * 32 + lane] = hp;
        __syncthreads();
        if (tid < 32 && hg == 0) {
            float o = wl[385];
#pragma unroll
            for (int s = 0; s < 8; s++) o += po_s[s * 32 + tid];
            out[(bg * 32 + tid) * NT + tprev] = o;
        }
    }
}

extern "C" void kernel_launch(void* const* d_in, const int* in_sizes, int n_in,
                              void* d_out, int out_size) {
    const float *x   = (const float *)d_in[0];
    const float *Wi1 = (const float *)d_in[1];
    const float *Wh1 = (const float *)d_in[2];
    const float *bi1 = (const float *)d_in[3];
    const float *bh1 = (const float *)d_in[4];
    const float *Wi2 = (const float *)d_in[5];
    const float *Wh2 = (const float *)d_in[6];
    const float *bi2 = (const float *)d_in[7];
    const float *bh2 = (const float *)d_in[8];
    const float *Wi3 = (const float *)d_in[9];
    const float *Wh3 = (const float *)d_in[10];
    const float *bi3 = (const float *)d_in[11];
    const float *bh3 = (const float *)d_in[12];
    const float *Wl  = (const float *)d_in[13];
    const float *bl  = (const float *)d_in[14];
    float *out = (float *)d_out;

    int T  = in_sizes[0] / BB;   // 1024
    int NT = out_size / BB;      // 1056

    cudaFuncSetAttribute(lstm_persist_kernel,
                         cudaFuncAttributeMaxDynamicSharedMemorySize, SMEM_BYTES);

    lstm_bar_init<<<1, 256>>>();
    lstm_persist_kernel<<<GRIDN, NTHR, SMEM_BYTES>>>(
        x, Wi1, Wh1, bi1, bh1, Wi2, Wh2, bi2, bh2,
        Wi3, Wh3, bi3, bh3, Wl, bl, out, T, NT);
}

// round 8
// speedup vs baseline: 1.4916x; 1.0707x over previous
#include <cuda_runtime.h>
#include <math.h>

// Problem shape (fixed): B=256, T=1024, H=128, FUTURE=32.
#define BB    256
#define HH    128
#define KK1   129          // cell1 input  [x, h1]
#define KK2   257          // cell2 input  [x, h1, h2]
#define KK3   385          // cell3 input  [x, h1, h2, h3]
#define GRIDN 128          // persistent CTAs, 1/SM, co-resident
#define NTHR  512          // 16 warps: 2 k-split sets x 8 row-warps

// ---------------- device-global exchange state (allocation-free) -------------
__device__ __align__(16) float g_h1[HH * BB];
__device__ __align__(16) float g_h2[HH * BB];
__device__ __align__(16) float g_h3[2][HH * BB];   // double buffer (deferred read)
__device__ unsigned g_flags[GRIDN * 32];           // one 128B line per CTA

__global__ void lstm_bar_init() {
    for (int i = threadIdx.x; i < GRIDN * 32; i += blockDim.x) g_flags[i] = 0u;
}

// ---------------- distributed flag barrier -----------------------------------
__device__ __forceinline__ void bar_arrive(unsigned p, int tid) {
    if (tid == 0) {
        __threadfence();
        asm volatile("st.relaxed.gpu.u32 [%0], %1;"
                     :: "l"(&g_flags[blockIdx.x * 32]), "r"(p) : "memory");
    }
}
__device__ __forceinline__ void bar_wait(unsigned p, int tid) {
    if (tid < GRIDN) {
        unsigned v;
        do {
            asm volatile("ld.relaxed.gpu.u32 %0, [%1];"
                         : "=r"(v) : "l"(&g_flags[tid * 32]) : "memory");
        } while (v < p);
    }
    __threadfence();
    __syncthreads();
}

// ---------------- activations (HW tanh) --------------------------------------
__device__ __forceinline__ float tanha(float x) {
    float r; asm("tanh.approx.f32 %0, %1;" : "=f"(r) : "f"(x)); return r;
}
__device__ __forceinline__ float sigf(float v) {
    return fmaf(0.5f, tanha(0.5f * v), 0.5f);
}

// ---------------- gate accumulation over a k-range ---------------------------
template <int K0, int K1>
__device__ __forceinline__ float4 accum_range(const float4 *__restrict__ wsq,
                                              float4 acc,
                                              const float *__restrict__ in_s,
                                              int lane, int j) {
    const float4 *wp = wsq + j;
    const float  *ip = in_s + lane;
#pragma unroll 4
    for (int k = K0; k < K1; k++) {
        float4 w = wp[k * 8];              // LDS.128 lane-uniform broadcast
        float  v = ip[k * 32];             // conflict-free LDS.32
        acc.x = fmaf(w.x, v, acc.x);
        acc.y = fmaf(w.y, v, acc.y);
        acc.z = fmaf(w.z, v, acc.z);
        acc.w = fmaf(w.w, v, acc.w);
    }
    return acc;
}

__device__ __forceinline__ float lstm_out(float4 a, float &c) {
    float ig = sigf(a.x), fg = sigf(a.y);
    float gg = tanha(a.z), og = sigf(a.w);
    c = fg * c + ig * gg;
    return og * tanha(c);
}

// combine the two k-set partials: set1 publishes, set0 sums. All threads call.
__device__ __forceinline__ float4 combine(float4 a, float4 *psum,
                                          int tid, int set) {
    if (set == 1) psum[tid - 256] = a;
    __syncthreads();
    if (set == 0) {
        float4 b = psum[tid];
        a.x += b.x; a.y += b.y; a.z += b.z; a.w += b.w;
    }
    return a;
}

// stage one h vector (this CTA's 32 cols, all 128 rows) L2 -> smem, vectorized
__device__ __forceinline__ void stage_h4(const float4 *__restrict__ src4,
                                         float4 *__restrict__ dst4, int tid) {
#pragma unroll
    for (int i = 0; i < 2; i++) {
        int idx = tid + i * NTHR;          // 0..1023
        int row = idx >> 3, q = idx & 7;
        dst4[row * 8 + q] = __ldcg(src4 + row * 64 + q);   // row stride 256 floats
    }
}

// ---------------- smem layout (floats) ---------------------------------------
#define WS1_F   (KK1 * 32)
#define WS2_F   (KK2 * 32)
#define WS3_F   (KK3 * 32)
#define BIAS_F  96
#define WL_F    392
#define BIG_F   (KK3 * 32)          // persistent [x|h1|h2|h3] prefix buffer
#define PO_F    512
#define OX_F    32
#define PSUM_F  1024                // 256 x float4 partial-combine buffer
#define SMEM_FLOATS (WS1_F + WS2_F + WS3_F + BIAS_F + WL_F + BIG_F + PO_F + OX_F + PSUM_F)
#define SMEM_BYTES  (SMEM_FLOATS * 4)

__global__ void __launch_bounds__(NTHR, 1)
lstm_persist_kernel(const float *__restrict__ x,
                    const float *__restrict__ Wi1, const float *__restrict__ Wh1,
                    const float *__restrict__ bi1, const float *__restrict__ bh1,
                    const float *__restrict__ Wi2, const float *__restrict__ Wh2,
                    const float *__restrict__ bi2, const float *__restrict__ bh2,
                    const float *__restrict__ Wi3, const float *__restrict__ Wh3,
                    const float *__restrict__ bi3, const float *__restrict__ bh3,
                    const float *__restrict__ Wl,  const float *__restrict__ bl,
                    float *__restrict__ out, int T, int NT) {
    extern __shared__ float sm[];
    float *ws1f  = sm;
    float *ws2f  = ws1f + WS1_F;
    float *ws3f  = ws2f + WS2_F;
    float *biasf = ws3f + WS3_F;
    float *wl    = biasf + BIAS_F;
    float *big   = wl + WL_F;
    float *po_s  = big + BIG_F;
    float *ox    = po_s + PO_F;
    float4 *psum = (float4 *)(ox + OX_F);

    const float4 *ws1 = (const float4 *)ws1f;
    const float4 *ws2 = (const float4 *)ws2f;
    const float4 *ws3 = (const float4 *)ws3f;
    const float4 *bias4 = (const float4 *)biasf;

    const int tid  = threadIdx.x;
    const int lane = tid & 31;
    const int wid  = tid >> 5;          // 0..15
    const int j    = wid & 7;           // local hidden row (0..7)
    const int set  = wid >> 3;          // k-split set: 0 or 1
    const int hg   = blockIdx.x & 15;   // hidden group (16 x 8 rows)
    const int bg   = blockIdx.x >> 4;   // batch group (8 x 32 cols)
    const int bcol = bg * 32 + lane;
    const int row  = hg * 8 + j;
    const int gidx = row * BB + bcol;
    const int sub  = wid;               // 16 head sub-slices
    const float4 zero4 = make_float4(0.f, 0.f, 0.f, 0.f);

    // ---- stage per-CTA weight slices once (layout [k][j][gate]) -------------
    for (int idx = tid; idx < WS1_F; idx += NTHR) {
        int k = idx >> 5, t5 = idx & 31, jj = t5 >> 2, g = t5 & 3;
        int r = g * HH + hg * 8 + jj;
        ws1f[idx] = (k == 0) ? Wi1[r] : Wh1[r * HH + (k - 1)];
    }
    for (int idx = tid; idx < WS2_F; idx += NTHR) {
        int k = idx >> 5, t5 = idx & 31, jj = t5 >> 2, g = t5 & 3;
        int r = g * HH + hg * 8 + jj;
        ws2f[idx] = (k < KK1) ? Wi2[r * KK1 + k] : Wh2[r * HH + (k - KK1)];
    }
    for (int idx = tid; idx < WS3_F; idx += NTHR) {
        int k = idx >> 5, t5 = idx & 31, jj = t5 >> 2, g = t5 & 3;
        int r = g * HH + hg * 8 + jj;
        ws3f[idx] = (k < 257) ? Wi3[r * 257 + k] : Wh3[r * HH + (k - 257)];
    }
    if (tid < 96) {
        int cell = tid >> 5, t5 = tid & 31, jj = t5 >> 2, g = t5 & 3;
        int r = g * HH + hg * 8 + jj;
        float b;
        if (cell == 0)      b = bi1[r] + bh1[r];
        else if (cell == 1) b = bi2[r] + bh2[r];
        else                b = bi3[r] + bh3[r];
        biasf[cell * 32 + t5] = b;
    }
    for (int idx = tid; idx < 385; idx += NTHR) wl[idx] = Wl[idx];
    if (tid == 0) wl[385] = bl[0];
    if (tid < 32) ox[tid] = 0.0f;
    for (int idx = tid; idx < BIG_F; idx += NTHR) big[idx] = 0.0f;
    __syncthreads();

    float c1 = 0.f, c2 = 0.f, c3 = 0.f;   // live in set0 only
    float hp = 0.f;                        // carried head partial (all threads)
    unsigned p = 0;

    float xr = 0.f;
    if (tid < 32) xr = __ldg(&x[(bg * 32 + tid) * T]);   // prefetch x(0)

    for (int t = 0; t < NT; t++) {
        // ---- deferred head of t-1 at TOP only when x(t) needs o(t-1) --------
        if (t > 0 && t >= T) {
            bar_wait(3u * (unsigned)t, tid);                   // wait3(t-1)
            stage_h4((const float4 *)&g_h3[(t - 1) & 1][bg * 32],
                     (float4 *)(big + 257 * 32), tid);
            __syncthreads();
            for (int k = 257 + sub; k < 385; k += 16)
                hp = fmaf(wl[k], big[k * 32 + lane], hp);
            po_s[sub * 32 + lane] = hp;
            __syncthreads();
            if (tid < 32) {
                float o = wl[385];
#pragma unroll
                for (int s = 0; s < 16; s++) o += po_s[s * 32 + tid];
                ox[tid] = o;
                if (hg == 0) out[(bg * 32 + tid) * NT + (t - 1)] = o;
            }
            __syncthreads();
        }

        // ---- x slot (h slots already hold h_prev) ---------------------------
        if (tid < 32) big[tid] = (t < T) ? xr : ox[tid];
        __syncthreads();

        // ================= cell 1 (x + h1_prev), k-split =====================
        float4 a1;
        if (set == 0) a1 = accum_range<0, 65>(ws1, bias4[0 * 8 + j], big, lane, j);
        else          a1 = accum_range<65, 129>(ws1, zero4, big, lane, j);
        a1 = combine(a1, psum, tid, set);
        if (set == 0) {
            float h1 = lstm_out(a1, c1);
            g_h1[gidx] = h1;
        }
        __syncthreads();
        p++; bar_arrive(p, tid);

        if (tid < 32 && t + 1 < T) xr = __ldg(&x[(bg * 32 + tid) * T + t + 1]);

        // overlap: cell2 partial over x (k=0) and h2_prev (k=129..257)
        float4 a2;
        if (set == 0) {
            a2 = accum_range<0, 1>(ws2, bias4[1 * 8 + j], big, lane, j);
            a2 = accum_range<129, 193>(ws2, a2, big, lane, j);
        } else {
            a2 = accum_range<193, 257>(ws2, zero4, big, lane, j);
        }

        bar_wait(p, tid);
        stage_h4((const float4 *)&g_h1[bg * 32], (float4 *)(big + 32), tid);
        __syncthreads();

        // ================= cell 2 (finish: h1_new), k-split ==================
        if (set == 0) a2 = accum_range<1, 65>(ws2, a2, big, lane, j);
        else          a2 = accum_range<65, 129>(ws2, a2, big, lane, j);
        a2 = combine(a2, psum, tid, set);
        if (set == 0) {
            float h2 = lstm_out(a2, c2);
            g_h2[gidx] = h2;
        }
        __syncthreads();
        p++; bar_arrive(p, tid);

        // ---- deferred head of t-1 (main path: wait3 is a guaranteed no-op) --
        if (t > 0 && t < T) {
            bar_wait(3u * (unsigned)t, tid);                   // already satisfied
            stage_h4((const float4 *)&g_h3[(t - 1) & 1][bg * 32],
                     (float4 *)(big + 257 * 32), tid);
            __syncthreads();
            for (int k = 257 + sub; k < 385; k += 16)
                hp = fmaf(wl[k], big[k * 32 + lane], hp);
            po_s[sub * 32 + lane] = hp;
            __syncthreads();
            if (tid < 32) {
                float o = wl[385];
#pragma unroll
                for (int s = 0; s < 16; s++) o += po_s[s * 32 + tid];
                ox[tid] = o;
                if (hg == 0) out[(bg * 32 + tid) * NT + (t - 1)] = o;
            }
            __syncthreads();
        }

        // overlap: cell3 partial over x + h1_new (0..129) and h3_prev (257..385)
        float4 a3;
        if (set == 0) {
            a3 = accum_range<0, 65>(ws3, bias4[2 * 8 + j], big, lane, j);
            a3 = accum_range<257, 321>(ws3, a3, big, lane, j);
        } else {
            a3 = accum_range<65, 129>(ws3, zero4, big, lane, j);
            a3 = accum_range<321, 385>(ws3, a3, big, lane, j);
        }

        bar_wait(p, tid);
        stage_h4((const float4 *)&g_h2[bg * 32], (float4 *)(big + 129 * 32), tid);
        __syncthreads();

        // ================= cell 3 (finish: h2_new), k-split ==================
        if (set == 0) a3 = accum_range<129, 193>(ws3, a3, big, lane, j);
        else          a3 = accum_range<193, 257>(ws3, a3, big, lane, j);
        a3 = combine(a3, psum, tid, set);
        if (set == 0) {
            float h3 = lstm_out(a3, c3);
            g_h3[t & 1][gidx] = h3;
        }
        __syncthreads();
        p++; bar_arrive(p, tid);

        // head partial over x,h1,h2 of step t (carried to next iteration)
        hp = 0.0f;
        for (int k = sub; k < 257; k += 16)
            hp = fmaf(wl[k], big[k * 32 + lane], hp);
    }

    // ---- epilogue: deferred head of the last step ---------------------------
    {
        int tprev = NT - 1;
        bar_wait(3u * (unsigned)NT, tid);
        stage_h4((const float4 *)&g_h3[tprev & 1][bg * 32],
                 (float4 *)(big + 257 * 32), tid);
        __syncthreads();
        for (int k = 257 + sub; k < 385; k += 16)
            hp = fmaf(wl[k], big[k * 32 + lane], hp);
        po_s[sub * 32 + lane] = hp;
        __syncthreads();
        if (tid < 32 && hg == 0) {
            float o = wl[385];
#pragma unroll
            for (int s = 0; s < 16; s++) o += po_s[s * 32 + tid];
            out[(bg * 32 + tid) * NT + tprev] = o;
        }
    }
}

extern "C" void kernel_launch(void* const* d_in, const int* in_sizes, int n_in,
                              void* d_out, int out_size) {
    const float *x   = (const float *)d_in[0];
    const float *Wi1 = (const float *)d_in[1];
    const float *Wh1 = (const float *)d_in[2];
    const float *bi1 = (const float *)d_in[3];
    const float *bh1 = (const float *)d_in[4];
    const float *Wi2 = (const float *)d_in[5];
    const float *Wh2 = (const float *)d_in[6];
    const float *bi2 = (const float *)d_in[7];
    const float *bh2 = (const float *)d_in[8];
    const float *Wi3 = (const float *)d_in[9];
    const float *Wh3 = (const float *)d_in[10];
    const float *bi3 = (const float *)d_in[11];
    const float *bh3 = (const float *)d_in[12];
    const float *Wl  = (const float *)d_in[13];
    const float *bl  = (const float *)d_in[14];
    float *out = (float *)d_out;

    int T  = in_sizes[0] / BB;   // 1024
    int NT = out_size / BB;      // 1056

    cudaFuncSetAttribute(lstm_persist_kernel,
                         cudaFuncAttributeMaxDynamicSharedMemorySize, SMEM_BYTES);

    lstm_bar_init<<<1, 256>>>();
    lstm_persist_kernel<<<GRIDN, NTHR, SMEM_BYTES>>>(
        x, Wi1, Wh1, bi1, bh1, Wi2, Wh2, bi2, bh2,
        Wi3, Wh3, bi3, bh3, Wl, bl, out, T, NT);
}

// round 9
// speedup vs baseline: 1.5723x; 1.0541x over previous
#include <cuda_runtime.h>
#include <math.h>

// Problem shape (fixed): B=256, T=1024, H=128, FUTURE=32.
#define BB    256
#define HH    128
#define KK1   129          // cell1 input  [x, h1]
#define KK2   257          // cell2 input  [x, h1, h2]
#define KK3   385          // cell3 input  [x, h1, h2, h3]
#define GRIDN 128          // persistent CTAs, 1/SM, co-resident
#define NTHR  512          // 16 warps: 4 k-split sets x 4 row-pair warps

// ---------------- device-global exchange state (allocation-free) -------------
__device__ __align__(16) float g_h1[HH * BB];
__device__ __align__(16) float g_h2[HH * BB];
__device__ __align__(16) float g_h3[2][HH * BB];   // double buffer (deferred read)
__device__ unsigned g_flags[GRIDN * 32];           // one 128B line per CTA

__global__ void lstm_bar_init() {
    for (int i = threadIdx.x; i < GRIDN * 32; i += blockDim.x) g_flags[i] = 0u;
}

// ---------------- distributed flag barrier -----------------------------------
__device__ __forceinline__ void bar_arrive(unsigned p, int tid) {
    if (tid == 0) {
        __threadfence();
        asm volatile("st.relaxed.gpu.u32 [%0], %1;"
                     :: "l"(&g_flags[blockIdx.x * 32]), "r"(p) : "memory");
    }
}
__device__ __forceinline__ void bar_wait(unsigned p, int tid) {
    if (tid < GRIDN) {
        unsigned v;
        do {
            asm volatile("ld.relaxed.gpu.u32 %0, [%1];"
                         : "=r"(v) : "l"(&g_flags[tid * 32]) : "memory");
        } while (v < p);
    }
    __threadfence();
    __syncthreads();
}

// ---------------- activations (HW tanh) --------------------------------------
__device__ __forceinline__ float tanha(float x) {
    float r; asm("tanh.approx.f32 %0, %1;" : "=f"(r) : "f"(x)); return r;
}
__device__ __forceinline__ float sigf(float v) {
    return fmaf(0.5f, tanha(0.5f * v), 0.5f);
}

// ---------------- gate accumulation: 2 rows x 4 gates per thread -------------
// ws : [k][rp(4)][rr(2)][gate(4)] floats = float4[k][8], index rp*2+rr
// in : [k][32] floats
template <int K0, int K1>
__device__ __forceinline__ void accum2(const float4 *__restrict__ wsq,
                                       float4 &a0, float4 &a1,
                                       const float *__restrict__ in_s,
                                       int lane, int rp) {
    const float4 *wp = wsq + rp * 2;
    const float  *ip = in_s + lane;
#pragma unroll 4
    for (int k = K0; k < K1; k++) {
        float4 w0 = wp[k * 8];             // LDS.128 broadcast (row rr=0)
        float4 w1 = wp[k * 8 + 1];         // LDS.128 broadcast (row rr=1)
        float  v  = ip[k * 32];            // conflict-free LDS.32
        a0.x = fmaf(w0.x, v, a0.x); a0.y = fmaf(w0.y, v, a0.y);
        a0.z = fmaf(w0.z, v, a0.z); a0.w = fmaf(w0.w, v, a0.w);
        a1.x = fmaf(w1.x, v, a1.x); a1.y = fmaf(w1.y, v, a1.y);
        a1.z = fmaf(w1.z, v, a1.z); a1.w = fmaf(w1.w, v, a1.w);
    }
}

__device__ __forceinline__ float lstm_out(float4 a, float &c) {
    float ig = sigf(a.x), fg = sigf(a.y);
    float gg = tanha(a.z), og = sigf(a.w);
    c = fg * c + ig * gg;
    return og * tanha(c);
}

// combine 4 k-set partials: sets 1..3 publish, set 0 sums. All threads call.
__device__ __forceinline__ void combine2(float4 &a0, float4 &a1,
                                         float4 *psum, int tid, int set) {
    int ts = tid & 127;
    if (set != 0) {
        psum[(set - 1) * 256 + ts * 2]     = a0;
        psum[(set - 1) * 256 + ts * 2 + 1] = a1;
    }
    __syncthreads();
    if (set == 0) {
#pragma unroll
        for (int s = 0; s < 3; s++) {
            float4 b0 = psum[s * 256 + ts * 2];
            float4 b1 = psum[s * 256 + ts * 2 + 1];
            a0.x += b0.x; a0.y += b0.y; a0.z += b0.z; a0.w += b0.w;
            a1.x += b1.x; a1.y += b1.y; a1.z += b1.z; a1.w += b1.w;
        }
    }
}

// stage one h vector (this CTA's 32 cols, all 128 rows) L2 -> smem, vectorized
__device__ __forceinline__ void stage_h4(const float4 *__restrict__ src4,
                                         float4 *__restrict__ dst4, int tid) {
#pragma unroll
    for (int i = 0; i < 2; i++) {
        int idx = tid + i * NTHR;          // 0..1023
        int row = idx >> 3, q = idx & 7;
        dst4[row * 8 + q] = __ldcg(src4 + row * 64 + q);   // row stride 256 floats
    }
}

// ---------------- smem layout (floats) ---------------------------------------
#define WS1_F   (KK1 * 32)
#define WS2_F   (KK2 * 32)
#define WS3_F   (KK3 * 32)
#define BIAS_F  96
#define WL_F    392
#define BIG_F   (KK3 * 32)          // persistent [x|h1|h2|h3] prefix buffer
#define PO_F    512
#define OX_F    32
#define PSUM_F  3072                // 3 sets x 128 thr x 2 float4
#define SMEM_FLOATS (WS1_F + WS2_F + WS3_F + BIAS_F + WL_F + BIG_F + PO_F + OX_F + PSUM_F)
#define SMEM_BYTES  (SMEM_FLOATS * 4)

__global__ void __launch_bounds__(NTHR, 1)
lstm_persist_kernel(const float *__restrict__ x,
                    const float *__restrict__ Wi1, const float *__restrict__ Wh1,
                    const float *__restrict__ bi1, const float *__restrict__ bh1,
                    const float *__restrict__ Wi2, const float *__restrict__ Wh2,
                    const float *__restrict__ bi2, const float *__restrict__ bh2,
                    const float *__restrict__ Wi3, const float *__restrict__ Wh3,
                    const float *__restrict__ bi3, const float *__restrict__ bh3,
                    const float *__restrict__ Wl,  const float *__restrict__ bl,
                    float *__restrict__ out, int T, int NT) {
    extern __shared__ float sm[];
    float *ws1f  = sm;
    float *ws2f  = ws1f + WS1_F;
    float *ws3f  = ws2f + WS2_F;
    float *biasf = ws3f + WS3_F;
    float *wl    = biasf + BIAS_F;
    float *big   = wl + WL_F;
    float *po_s  = big + BIG_F;
    float *ox    = po_s + PO_F;
    float4 *psum = (float4 *)(ox + OX_F);

    const float4 *ws1 = (const float4 *)ws1f;
    const float4 *ws2 = (const float4 *)ws2f;
    const float4 *ws3 = (const float4 *)ws3f;
    const float4 *bias4 = (const float4 *)biasf;

    const int tid  = threadIdx.x;
    const int lane = tid & 31;
    const int wid  = tid >> 5;          // 0..15
    const int rp   = wid & 3;           // row-pair: rows 2rp, 2rp+1
    const int set  = wid >> 2;          // k-split set: 0..3
    const int hg   = blockIdx.x & 15;   // hidden group (16 x 8 rows)
    const int bg   = blockIdx.x >> 4;   // batch group (8 x 32 cols)
    const int bcol = bg * 32 + lane;
    const int gidx0 = (hg * 8 + rp * 2) * BB + bcol;       // row rr=0
    const int sub  = wid;               // 16 head sub-slices
    const float4 zero4 = make_float4(0.f, 0.f, 0.f, 0.f);

    // ---- stage per-CTA weight slices once; layout [k][rp][rr][gate] ---------
    for (int idx = tid; idx < WS1_F; idx += NTHR) {
        int k = idx >> 5, t5 = idx & 31;
        int rpp = t5 >> 3, rr = (t5 >> 2) & 1, g = t5 & 3;
        int r = g * HH + hg * 8 + rpp * 2 + rr;
        ws1f[idx] = (k == 0) ? Wi1[r] : Wh1[r * HH + (k - 1)];
    }
    for (int idx = tid; idx < WS2_F; idx += NTHR) {
        int k = idx >> 5, t5 = idx & 31;
        int rpp = t5 >> 3, rr = (t5 >> 2) & 1, g = t5 & 3;
        int r = g * HH + hg * 8 + rpp * 2 + rr;
        ws2f[idx] = (k < KK1) ? Wi2[r * KK1 + k] : Wh2[r * HH + (k - KK1)];
    }
    for (int idx = tid; idx < WS3_F; idx += NTHR) {
        int k = idx >> 5, t5 = idx & 31;
        int rpp = t5 >> 3, rr = (t5 >> 2) & 1, g = t5 & 3;
        int r = g * HH + hg * 8 + rpp * 2 + rr;
        ws3f[idx] = (k < 257) ? Wi3[r * 257 + k] : Wh3[r * HH + (k - 257)];
    }
    if (tid < 96) {
        int cell = tid >> 5, t5 = tid & 31;
        int rpp = t5 >> 3, rr = (t5 >> 2) & 1, g = t5 & 3;
        int r = g * HH + hg * 8 + rpp * 2 + rr;
        float b;
        if (cell == 0)      b = bi1[r] + bh1[r];
        else if (cell == 1) b = bi2[r] + bh2[r];
        else                b = bi3[r] + bh3[r];
        biasf[cell * 32 + t5] = b;
    }
    for (int idx = tid; idx < 385; idx += NTHR) wl[idx] = Wl[idx];
    if (tid == 0) wl[385] = bl[0];
    if (tid < 32) ox[tid] = 0.0f;
    for (int idx = tid; idx < BIG_F; idx += NTHR) big[idx] = 0.0f;
    __syncthreads();

    float c1a = 0.f, c1b = 0.f, c2a = 0.f, c2b = 0.f, c3a = 0.f, c3b = 0.f;
    float hp = 0.f;                      // carried head partial (all threads)
    unsigned p = 0;

    float xr = 0.f;
    if (tid < 32) xr = __ldg(&x[(bg * 32 + tid) * T]);   // prefetch x(0)

    for (int t = 0; t < NT; t++) {
        // ---- deferred head of t-1 at TOP only when x(t) needs o(t-1) --------
        if (t > 0 && t >= T) {
            bar_wait(3u * (unsigned)t, tid);                   // wait3(t-1)
            stage_h4((const float4 *)&g_h3[(t - 1) & 1][bg * 32],
                     (float4 *)(big + 257 * 32), tid);
            __syncthreads();
            for (int k = 257 + sub; k < 385; k += 16)
                hp = fmaf(wl[k], big[k * 32 + lane], hp);
            po_s[sub * 32 + lane] = hp;
            __syncthreads();
            if (tid < 32) {
                float o = wl[385];
#pragma unroll
                for (int s = 0; s < 16; s++) o += po_s[s * 32 + tid];
                ox[tid] = o;
                if (hg == 0) out[(bg * 32 + tid) * NT + (t - 1)] = o;
            }
            __syncthreads();
        }

        // ---- x slot (h slots already hold h_prev) ---------------------------
        if (tid < 32) big[tid] = (t < T) ? xr : ox[tid];
        __syncthreads();

        // ================= cell 1 (x + h1_prev), 4-way k-split ===============
        float4 a0, a1;
        if (set == 0) {
            a0 = bias4[0 * 8 + rp * 2]; a1 = bias4[0 * 8 + rp * 2 + 1];
            accum2<0, 33>(ws1, a0, a1, big, lane, rp);
        } else {
            a0 = zero4; a1 = zero4;
            if (set == 1)      accum2<33, 65>(ws1, a0, a1, big, lane, rp);
            else if (set == 2) accum2<65, 97>(ws1, a0, a1, big, lane, rp);
            else               accum2<97, 129>(ws1, a0, a1, big, lane, rp);
        }
        combine2(a0, a1, psum, tid, set);
        if (set == 0) {
            g_h1[gidx0]      = lstm_out(a0, c1a);
            g_h1[gidx0 + BB] = lstm_out(a1, c1b);
        }
        __syncthreads();
        p++; bar_arrive(p, tid);

        if (tid < 32 && t + 1 < T) xr = __ldg(&x[(bg * 32 + tid) * T + t + 1]);

        // overlap: cell2 partial over x (k=0) and h2_prev (129..257)
        float4 b0, b1;
        if (set == 0) {
            b0 = bias4[1 * 8 + rp * 2]; b1 = bias4[1 * 8 + rp * 2 + 1];
            accum2<0, 1>(ws2, b0, b1, big, lane, rp);
            accum2<129, 161>(ws2, b0, b1, big, lane, rp);
        } else {
            b0 = zero4; b1 = zero4;
            if (set == 1)      accum2<161, 193>(ws2, b0, b1, big, lane, rp);
            else if (set == 2) accum2<193, 225>(ws2, b0, b1, big, lane, rp);
            else               accum2<225, 257>(ws2, b0, b1, big, lane, rp);
        }

        bar_wait(p, tid);
        stage_h4((const float4 *)&g_h1[bg * 32], (float4 *)(big + 32), tid);
        __syncthreads();

        // ================= cell 2 (finish: h1_new) ===========================
        if (set == 0)      accum2<1, 33>(ws2, b0, b1, big, lane, rp);
        else if (set == 1) accum2<33, 65>(ws2, b0, b1, big, lane, rp);
        else if (set == 2) accum2<65, 97>(ws2, b0, b1, big, lane, rp);
        else               accum2<97, 129>(ws2, b0, b1, big, lane, rp);
        combine2(b0, b1, psum, tid, set);
        if (set == 0) {
            g_h2[gidx0]      = lstm_out(b0, c2a);
            g_h2[gidx0 + BB] = lstm_out(b1, c2b);
        }
        __syncthreads();
        p++; bar_arrive(p, tid);

        // ---- deferred head of t-1 (main path: wait3 is a guaranteed no-op) --
        if (t > 0 && t < T) {
            bar_wait(3u * (unsigned)t, tid);                   // already satisfied
            stage_h4((const float4 *)&g_h3[(t - 1) & 1][bg * 32],
                     (float4 *)(big + 257 * 32), tid);
            __syncthreads();
            for (int k = 257 + sub; k < 385; k += 16)
                hp = fmaf(wl[k], big[k * 32 + lane], hp);
            po_s[sub * 32 + lane] = hp;
            __syncthreads();
            if (tid < 32) {
                float o = wl[385];
#pragma unroll
                for (int s = 0; s < 16; s++) o += po_s[s * 32 + tid];
                ox[tid] = o;
                if (hg == 0) out[(bg * 32 + tid) * NT + (t - 1)] = o;
            }
            __syncthreads();
        }

        // overlap: cell3 partial over x + h1_new (0..129) and h3_prev (257..385)
        float4 d0, d1;
        if (set == 0) {
            d0 = bias4[2 * 8 + rp * 2]; d1 = bias4[2 * 8 + rp * 2 + 1];
            accum2<0, 33>(ws3, d0, d1, big, lane, rp);
            accum2<257, 289>(ws3, d0, d1, big, lane, rp);
        } else {
            d0 = zero4; d1 = zero4;
            if (set == 1) {
                accum2<33, 65>(ws3, d0, d1, big, lane, rp);
                accum2<289, 321>(ws3, d0, d1, big, lane, rp);
            } else if (set == 2) {
                accum2<65, 97>(ws3, d0, d1, big, lane, rp);
                accum2<321, 353>(ws3, d0, d1, big, lane, rp);
            } else {
                accum2<97, 129>(ws3, d0, d1, big, lane, rp);
                accum2<353, 385>(ws3, d0, d1, big, lane, rp);
            }
        }

        bar_wait(p, tid);
        stage_h4((const float4 *)&g_h2[bg * 32], (float4 *)(big + 129 * 32), tid);
        __syncthreads();

        // ================= cell 3 (finish: h2_new) ===========================
        if (set == 0)      accum2<129, 161>(ws3, d0, d1, big, lane, rp);
        else if (set == 1) accum2<161, 193>(ws3, d0, d1, big, lane, rp);
        else if (set == 2) accum2<193, 225>(ws3, d0, d1, big, lane, rp);
        else               accum2<225, 257>(ws3, d0, d1, big, lane, rp);
        combine2(d0, d1, psum, tid, set);
        if (set == 0) {
            g_h3[t & 1][gidx0]      = lstm_out(d0, c3a);
            g_h3[t & 1][gidx0 + BB] = lstm_out(d1, c3b);
        }
        __syncthreads();
        p++; bar_arrive(p, tid);

        // head partial over x,h1,h2 of step t (carried to next iteration)
        hp = 0.0f;
        for (int k = sub; k < 257; k += 16)
            hp = fmaf(wl[k], big[k * 32 + lane], hp);
    }

    // ---- epilogue: deferred head of the last step ---------------------------
    {
        int tprev = NT - 1;
        bar_wait(3u * (unsigned)NT, tid);
        stage_h4((const float4 *)&g_h3[tprev & 1][bg * 32],
                 (float4 *)(big + 257 * 32), tid);
        __syncthreads();
        for (int k = 257 + sub; k < 385; k += 16)
            hp = fmaf(wl[k], big[k * 32 + lane], hp);
        po_s[sub * 32 + lane] = hp;
        __syncthreads();
        if (tid < 32 && hg == 0) {
            float o = wl[385];
#pragma unroll
            for (int s = 0; s < 16; s++) o += po_s[s * 32 + tid];
            out[(bg * 32 + tid) * NT + tprev] = o;
        }
    }
}

extern "C" void kernel_launch(void* const* d_in, const int* in_sizes, int n_in,
                              void* d_out, int out_size) {
    const float *x   = (const float *)d_in[0];
    const float *Wi1 = (const float *)d_in[1];
    const float *Wh1 = (const float *)d_in[2];
    const float *bi1 = (const float *)d_in[3];
    const float *bh1 = (const float *)d_in[4];
    const float *Wi2 = (const float *)d_in[5];
    const float *Wh2 = (const float *)d_in[6];
    const float *bi2 = (const float *)d_in[7];
    const float *bh2 = (const float *)d_in[8];
    const float *Wi3 = (const float *)d_in[9];
    const float *Wh3 = (const float *)d_in[10];
    const float *bi3 = (const float *)d_in[11];
    const float *bh3 = (const float *)d_in[12];
    const float *Wl  = (const float *)d_in[13];
    const float *bl  = (const float *)d_in[14];
    float *out = (float *)d_out;

    int T  = in_sizes[0] / BB;   // 1024
    int NT = out_size / BB;      // 1056

    cudaFuncSetAttribute(lstm_persist_kernel,
                         cudaFuncAttributeMaxDynamicSharedMemorySize, SMEM_BYTES);

    lstm_bar_init<<<1, 256>>>();
    lstm_persist_kernel<<<GRIDN, NTHR, SMEM_BYTES>>>(
        x, Wi1, Wh1, bi1, bh1, Wi2, Wh2, bi2, bh2,
        Wi3, Wh3, bi3, bh3, Wl, bl, out, T, NT);
}

// round 10
// speedup vs baseline: 1.6673x; 1.0604x over previous
#include <cuda_runtime.h>
#include <math.h>

// Problem shape (fixed): B=256, T=1024, H=128, FUTURE=32.
#define BB    256
#define HH    128
#define KK1   129          // cell1 input  [x, h1]
#define KK2   257          // cell2 input  [x, h1, h2]
#define KK3   385          // cell3 input  [x, h1, h2, h3]
#define GRIDN 128          // 64 Galpha (cell1+cell2) + 64 Gbeta (cell3+head)
#define NTHR  512          // 16 warps: 8 row-pair warps x 2 k-sets

// ---------------- device-global exchange state (allocation-free) -------------
__device__ __align__(16) float g_h1[2][HH * BB];
__device__ __align__(16) float g_h2[2][HH * BB];
__device__ __align__(16) float g_h3[2][HH * BB];
__device__ __align__(16) float g_ox[BB];
__device__ int g_flags[256 * 32];   // 128B-strided lines:
// [0..63]    alpha phase   (2t+1 after h1(t), 2t+2 after h2(t))
// [64..127]  beta intra    (t+1 after h3(t) stored)
// [128..191] beta consumed (t+1 after beta staged h1(t),h2(t))
// [192..199] o ready       (t+1 after o(t) in g_ox), one line per bg

__global__ void lstm_bar_init() {
    for (int i = threadIdx.x; i < 256 * 32; i += blockDim.x) g_flags[i] = 0;
}

// ---------------- flags ------------------------------------------------------
__device__ __forceinline__ void flag_set(int line, int val, int tid) {
    if (tid == 0) {
        __threadfence();
        asm volatile("st.relaxed.gpu.s32 [%0], %1;"
                     :: "l"(g_flags + line * 32), "r"(val) : "memory");
    }
}
__device__ __forceinline__ void flag_wait(int line0, int n, int target, int tid) {
    if (tid < n) {
        int v;
        do {
            asm volatile("ld.relaxed.gpu.s32 %0, [%1];"
                         : "=r"(v) : "l"(g_flags + (line0 + tid) * 32) : "memory");
        } while (v < target);
    }
    __threadfence();
    __syncthreads();
}

// ---------------- activations (HW tanh) --------------------------------------
__device__ __forceinline__ float tanha(float x) {
    float r; asm("tanh.approx.f32 %0, %1;" : "=f"(r) : "f"(x)); return r;
}
__device__ __forceinline__ float sigf(float v) {
    return fmaf(0.5f, tanha(0.5f * v), 0.5f);
}
__device__ __forceinline__ float lstm_out(float4 a, float &c) {
    float ig = sigf(a.x), fg = sigf(a.y);
    float gg = tanha(a.z), og = sigf(a.w);
    c = fg * c + ig * gg;
    return og * tanha(c);
}

// ---------------- gate accumulation: 2 rows x 4 gates per thread -------------
// ws: [k][rp(8)][rr(2)][gate(4)] floats = float4[k][16]
template <int K0, int K1>
__device__ __forceinline__ void accum2(const float4 *__restrict__ wsq,
                                       float4 &a0, float4 &a1,
                                       const float *__restrict__ in_s,
                                       int lane, int rp) {
    const float4 *wp = wsq + rp * 2;
    const float  *ip = in_s + lane;
#pragma unroll 4
    for (int k = K0; k < K1; k++) {
        float4 w0 = wp[k * 16];            // LDS.128 broadcast (row rr=0)
        float4 w1 = wp[k * 16 + 1];        // LDS.128 broadcast (row rr=1)
        float  v  = ip[k * 32];            // conflict-free LDS.32
        a0.x = fmaf(w0.x, v, a0.x); a0.y = fmaf(w0.y, v, a0.y);
        a0.z = fmaf(w0.z, v, a0.z); a0.w = fmaf(w0.w, v, a0.w);
        a1.x = fmaf(w1.x, v, a1.x); a1.y = fmaf(w1.y, v, a1.y);
        a1.z = fmaf(w1.z, v, a1.z); a1.w = fmaf(w1.w, v, a1.w);
    }
}

// combine 2 k-set partials: set1 publishes, set0 sums. All threads call.
__device__ __forceinline__ void combine2(float4 &a0, float4 &a1,
                                         float4 *psum, int tid, int set) {
    if (set == 1) {
        psum[(tid - 256) * 2]     = a0;
        psum[(tid - 256) * 2 + 1] = a1;
    }
    __syncthreads();
    if (set == 0) {
        float4 b0 = psum[tid * 2], b1 = psum[tid * 2 + 1];
        a0.x += b0.x; a0.y += b0.y; a0.z += b0.z; a0.w += b0.w;
        a1.x += b1.x; a1.y += b1.y; a1.z += b1.z; a1.w += b1.w;
    }
}

// stage one h vector (this CTA's 32 cols, 128 rows) L2 -> smem slot
__device__ __forceinline__ void stage_h(const float *__restrict__ src,
                                        float *__restrict__ dst, int tid) {
    const float4 *s4 = (const float4 *)src;
    float4 *d4 = (float4 *)dst;
#pragma unroll
    for (int i = 0; i < 2; i++) {
        int idx = tid + i * NTHR;          // 0..1023
        int row = idx >> 3, q = idx & 7;
        d4[row * 8 + q] = __ldcg(s4 + row * 64 + q);   // row stride 256 floats
    }
}

// ---------------- smem layouts (floats) --------------------------------------
// Galpha: ws1(129*64) ws2(257*64) bias(128) big(257*32) psum(2048)
// Gbeta : ws3(385*64) bias(64) wl(392) big(385*32) po(512) ox(32) psum(2048)
#define SMA_F (129*64 + 257*64 + 128 + 257*32 + 2048 + 32)
#define SMB_F (385*64 + 64 + 392 + 385*32 + 512 + 32 + 2048 + 32)
#define SMEM_F (SMB_F > SMA_F ? SMB_F : SMA_F)
#define SMEM_BYTES (SMEM_F * 4)

__global__ void __launch_bounds__(NTHR, 1)
lstm_pipe_kernel(const float *__restrict__ x,
                 const float *__restrict__ Wi1, const float *__restrict__ Wh1,
                 const float *__restrict__ bi1, const float *__restrict__ bh1,
                 const float *__restrict__ Wi2, const float *__restrict__ Wh2,
                 const float *__restrict__ bi2, const float *__restrict__ bh2,
                 const float *__restrict__ Wi3, const float *__restrict__ Wh3,
                 const float *__restrict__ bi3, const float *__restrict__ bh3,
                 const float *__restrict__ Wl,  const float *__restrict__ bl,
                 float *__restrict__ out, int T, int NT) {
    extern __shared__ float sm[];
    const int tid  = threadIdx.x;
    const int lane = tid & 31;
    const int wid  = tid >> 5;          // 0..15
    const int rp   = wid & 7;           // row-pair slot: rows 2rp, 2rp+1 (of 16)
    const int set  = wid >> 3;          // k-split set: 0,1
    const float4 zero4 = make_float4(0.f, 0.f, 0.f, 0.f);

    if (blockIdx.x < 64) {
        // =================== Galpha : cell1 + cell2 ==========================
        const int aid = blockIdx.x;
        const int hg = aid & 7, bg = aid >> 3;
        const int bcol = bg * 32 + lane;

        float *ws1f  = sm;
        float *ws2f  = ws1f + 129 * 64;
        float *biasf = ws2f + 257 * 64;
        float *big   = biasf + 128;
        float4 *psum = (float4 *)(big + 257 * 32);
        const float4 *ws1 = (const float4 *)ws1f;
        const float4 *ws2 = (const float4 *)ws2f;
        const float4 *bias4 = (const float4 *)biasf;

        for (int idx = tid; idx < 129 * 64; idx += NTHR) {
            int k = idx >> 6, t6 = idx & 63;
            int rpp = t6 >> 3, rr = (t6 >> 2) & 1, g = t6 & 3;
            int r = g * HH + hg * 16 + rpp * 2 + rr;
            ws1f[idx] = (k == 0) ? Wi1[r] : Wh1[r * HH + (k - 1)];
        }
        for (int idx = tid; idx < 257 * 64; idx += NTHR) {
            int k = idx >> 6, t6 = idx & 63;
            int rpp = t6 >> 3, rr = (t6 >> 2) & 1, g = t6 & 3;
            int r = g * HH + hg * 16 + rpp * 2 + rr;
            ws2f[idx] = (k < KK1) ? Wi2[r * KK1 + k] : Wh2[r * HH + (k - KK1)];
        }
        if (tid < 128) {
            int cell = tid >> 6, t6 = tid & 63;
            int rpp = t6 >> 3, rr = (t6 >> 2) & 1, g = t6 & 3;
            int r = g * HH + hg * 16 + rpp * 2 + rr;
            biasf[tid] = cell ? (bi2[r] + bh2[r]) : (bi1[r] + bh1[r]);
        }
        for (int idx = tid; idx < 257 * 32; idx += NTHR) big[idx] = 0.0f;
        __syncthreads();

        float c1a = 0.f, c1b = 0.f, c2a = 0.f, c2b = 0.f;
        const int gr0 = (hg * 16 + rp * 2) * BB + bcol;   // global h index, rr=0
        float xr = 0.f;
        if (tid < 32) xr = __ldg(&x[(bg * 32 + tid) * T]);

        for (int t = 0; t < NT; t++) {
            // backpressure: beta consumed h1/h2(t-2) (steady-state free)
            flag_wait(128, 64, t - 1, tid);
            // x slot
            if (t >= T) {
                if (tid == 0) {
                    int v;
                    do {
                        asm volatile("ld.relaxed.gpu.s32 %0, [%1];"
                                     : "=r"(v) : "l"(g_flags + (192 + bg) * 32) : "memory");
                    } while (v < t);
                }
                __threadfence();
                __syncthreads();
                if (tid < 32) big[tid] = __ldcg(&g_ox[bg * 32 + tid]);
            } else {
                if (tid < 32) big[tid] = xr;
            }
            __syncthreads();

            // ---- cell 1 (x + h1_prev slot, persistent) ----------------------
            float4 a0, a1;
            if (set == 0) {
                a0 = bias4[rp * 2]; a1 = bias4[rp * 2 + 1];
                accum2<0, 65>(ws1, a0, a1, big, lane, rp);
            } else {
                a0 = zero4; a1 = zero4;
                accum2<65, 129>(ws1, a0, a1, big, lane, rp);
            }
            combine2(a0, a1, psum, tid, set);
            if (set == 0) {
                g_h1[t & 1][gr0]      = lstm_out(a0, c1a);
                g_h1[t & 1][gr0 + BB] = lstm_out(a1, c1b);
            }
            __syncthreads();
            flag_set(aid, 2 * t + 1, tid);

            if (tid < 32 && t + 1 < T) xr = __ldg(&x[(bg * 32 + tid) * T + t + 1]);

            // old-phase wait (nearly free) then stage h2(t-1)
            flag_wait(0, 64, 2 * t, tid);
            if (t > 0) {
                stage_h(&g_h2[(t - 1) & 1][bg * 32], big + 129 * 32, tid);
            }
            __syncthreads();

            // ---- cell2 partial over x (k=0) + h2_prev (129..257) ------------
            float4 b0, b1;
            if (set == 0) {
                b0 = bias4[16 + rp * 2]; b1 = bias4[16 + rp * 2 + 1];
                accum2<0, 1>(ws2, b0, b1, big, lane, rp);
                accum2<129, 193>(ws2, b0, b1, big, lane, rp);
            } else {
                b0 = zero4; b1 = zero4;
                accum2<193, 257>(ws2, b0, b1, big, lane, rp);
            }

            flag_wait(0, 64, 2 * t + 1, tid);          // h1(t) from all peers
            stage_h(&g_h1[t & 1][bg * 32], big + 32, tid);
            __syncthreads();

            // ---- cell 2 finish over h1_new (1..129) -------------------------
            if (set == 0) accum2<1, 65>(ws2, b0, b1, big, lane, rp);
            else          accum2<65, 129>(ws2, b0, b1, big, lane, rp);
            combine2(b0, b1, psum, tid, set);
            if (set == 0) {
                g_h2[t & 1][gr0]      = lstm_out(b0, c2a);
                g_h2[t & 1][gr0 + BB] = lstm_out(b1, c2b);
            }
            __syncthreads();
            flag_set(aid, 2 * t + 2, tid);
        }
    } else {
        // =================== Gbeta : cell3 + head ============================
        const int bidx = blockIdx.x - 64;
        const int hg = bidx & 7, bg = bidx >> 3;
        const int bcol = bg * 32 + lane;
        const int sub = wid;

        float *ws3f  = sm;
        float *biasf = ws3f + 385 * 64;
        float *wl    = biasf + 64;
        float *big   = wl + 392;
        float *po_s  = big + 385 * 32;
        float *ox    = po_s + 512;
        float4 *psum = (float4 *)(ox + 32);
        const float4 *ws3 = (const float4 *)ws3f;
        const float4 *bias4 = (const float4 *)biasf;

        for (int idx = tid; idx < 385 * 64; idx += NTHR) {
            int k = idx >> 6, t6 = idx & 63;
            int rpp = t6 >> 3, rr = (t6 >> 2) & 1, g = t6 & 3;
            int r = g * HH + hg * 16 + rpp * 2 + rr;
            ws3f[idx] = (k < 257) ? Wi3[r * 257 + k] : Wh3[r * HH + (k - 257)];
        }
        if (tid < 64) {
            int t6 = tid;
            int rpp = t6 >> 3, rr = (t6 >> 2) & 1, g = t6 & 3;
            int r = g * HH + hg * 16 + rpp * 2 + rr;
            biasf[tid] = bi3[r] + bh3[r];
        }
        for (int idx = tid; idx < 385; idx += NTHR) wl[idx] = Wl[idx];
        if (tid == 0) wl[385] = bl[0];
        if (tid < 32) ox[tid] = 0.0f;
        for (int idx = tid; idx < 385 * 32; idx += NTHR) big[idx] = 0.0f;
        __syncthreads();

        float c3a = 0.f, c3b = 0.f;
        const int gr0 = (hg * 16 + rp * 2) * BB + bcol;
        float xr = 0.f;
        if (tid < 32) xr = __ldg(&x[(bg * 32 + tid) * T]);

        for (int t = 0; t < NT; t++) {
            // x slot: own head produced o(t-1) locally for the tail
            if (tid < 32) big[tid] = (t < T) ? xr : ox[tid];
            __syncthreads();

            // ---- cell3 partial over x (k=0) + h3_prev (257..385, persistent)
            float4 d0, d1;
            if (set == 0) {
                d0 = bias4[rp * 2]; d1 = bias4[rp * 2 + 1];
                accum2<0, 1>(ws3, d0, d1, big, lane, rp);
                accum2<257, 321>(ws3, d0, d1, big, lane, rp);
            } else {
                d0 = zero4; d1 = zero4;
                accum2<321, 385>(ws3, d0, d1, big, lane, rp);
            }

            flag_wait(0, 64, 2 * t + 2, tid);          // alpha step t fully done
            stage_h(&g_h1[t & 1][bg * 32], big + 32, tid);
            stage_h(&g_h2[t & 1][bg * 32], big + 129 * 32, tid);
            __syncthreads();
            flag_set(128 + bidx, t + 1, tid);          // buffers consumed

            if (tid < 32 && t + 1 < T) xr = __ldg(&x[(bg * 32 + tid) * T + t + 1]);

            // ---- cell 3 finish over h1,h2 (1..257) --------------------------
            if (set == 0) accum2<1, 129>(ws3, d0, d1, big, lane, rp);
            else          accum2<129, 257>(ws3, d0, d1, big, lane, rp);
            combine2(d0, d1, psum, tid, set);
            if (set == 0) {
                g_h3[t & 1][gr0]      = lstm_out(d0, c3a);
                g_h3[t & 1][gr0 + BB] = lstm_out(d1, c3b);
            }
            __syncthreads();
            flag_set(64 + bidx, t + 1, tid);           // intra-beta arrive

            // head partial over x,h1,h2 while peers store h3
            float hp = 0.0f;
            for (int k = sub; k < 257; k += 16)
                hp = fmaf(wl[k], big[k * 32 + lane], hp);

            flag_wait(64, 64, t + 1, tid);             // intra-beta wait
            stage_h(&g_h3[t & 1][bg * 32], big + 257 * 32, tid);  // persists to t+1
            __syncthreads();

            for (int k = 257 + sub; k < 385; k += 16)
                hp = fmaf(wl[k], big[k * 32 + lane], hp);
            po_s[sub * 32 + lane] = hp;
            __syncthreads();
            if (tid < 32) {
                float o = wl[385];
#pragma unroll
                for (int s = 0; s < 16; s++) o += po_s[s * 32 + tid];
                ox[tid] = o;
                if (hg == 0) {
                    out[(bg * 32 + tid) * NT + t] = o;
                    g_ox[bg * 32 + tid] = o;
                }
            }
            __syncthreads();
            if (hg == 0) flag_set(192 + bg, t + 1, tid);
        }
    }
}

extern "C" void kernel_launch(void* const* d_in, const int* in_sizes, int n_in,
                              void* d_out, int out_size) {
    const float *x   = (const float *)d_in[0];
    const float *Wi1 = (const float *)d_in[1];
    const float *Wh1 = (const float *)d_in[2];
    const float *bi1 = (const float *)d_in[3];
    const float *bh1 = (const float *)d_in[4];
    const float *Wi2 = (const float *)d_in[5];
    const float *Wh2 = (const float *)d_in[6];
    const float *bi2 = (const float *)d_in[7];
    const float *bh2 = (const float *)d_in[8];
    const float *Wi3 = (const float *)d_in[9];
    const float *Wh3 = (const float *)d_in[10];
    const float *bi3 = (const float *)d_in[11];
    const float *bh3 = (const float *)d_in[12];
    const float *Wl  = (const float *)d_in[13];
    const float *bl  = (const float *)d_in[14];
    float *out = (float *)d_out;

    int T  = in_sizes[0] / BB;   // 1024
    int NT = out_size / BB;      // 1056

    cudaFuncSetAttribute(lstm_pipe_kernel,
                         cudaFuncAttributeMaxDynamicSharedMemorySize, SMEM_BYTES);

    lstm_bar_init<<<1, 256>>>();
    lstm_pipe_kernel<<<GRIDN, NTHR, SMEM_BYTES>>>(
        x, Wi1, Wh1, bi1, bh1, Wi2, Wh2, bi2, bh2,
        Wi3, Wh3, bi3, bh3, Wl, bl, out, T, NT);
}

// round 11
// speedup vs baseline: 1.7371x; 1.0418x over previous
#include <cuda_runtime.h>
#include <math.h>

// Problem shape (fixed): B=256, T=1024, H=128, FUTURE=32.
#define BB    256
#define HH    128
#define KK1   129
#define KK2   257
#define KK3   385
#define NTHR  256          // 8 warps: 4 row-pair warps x 2 k-sets
// 256 CTAs: 0..127 alpha (cell1+cell2, 8 rows), 128..255 beta (cell3+head)

// ---------------- device-global exchange state (allocation-free) -------------
__device__ __align__(16) float g_h1[2][HH * BB];
__device__ __align__(16) float g_h2[2][HH * BB];
__device__ __align__(16) float g_h3[2][HH * BB];
__device__ __align__(16) float g_ox[BB];
__device__ int g_flags[392 * 32];
// lines 0..127    : alpha(hg*8+bg)  -> 2t+1 after h1(t), 2t+2 after h2(t)
// lines 128..255  : beta intra      -> t+1 after h3(t) stored
// lines 256..383  : beta consumed   -> t+1 after staging h1(t),h2(t)
// lines 384..391  : o ready per bg  -> t+1 after o(t) in g_ox

__global__ void lstm_bar_init() {
    for (int i = threadIdx.x; i < 392 * 32; i += blockDim.x) g_flags[i] = 0;
}

// ---------------- flags ------------------------------------------------------
__device__ __forceinline__ void flag_set(int line, int val, int tid) {
    if (tid == 0) {
        __threadfence();
        asm volatile("st.relaxed.gpu.s32 [%0], %1;"
                     :: "l"(g_flags + line * 32), "r"(val) : "memory");
    }
}
// wait on the 16 same-bg lines {base + h*8 + bg : h=0..15}
__device__ __forceinline__ void flag_wait16(int base, int bg, int target, int tid) {
    if (tid < 16) {
        int v;
        const int *fp = g_flags + (base + tid * 8 + bg) * 32;
        do {
            asm volatile("ld.relaxed.gpu.s32 %0, [%1];" : "=r"(v) : "l"(fp) : "memory");
        } while (v < target);
    }
    __threadfence();
    __syncthreads();
}
__device__ __forceinline__ void flag_wait1(int line, int target, int tid) {
    if (tid == 0) {
        int v;
        const int *fp = g_flags + line * 32;
        do {
            asm volatile("ld.relaxed.gpu.s32 %0, [%1];" : "=r"(v) : "l"(fp) : "memory");
        } while (v < target);
    }
    __threadfence();
    __syncthreads();
}

// ---------------- activations (HW tanh) --------------------------------------
__device__ __forceinline__ float tanha(float x) {
    float r; asm("tanh.approx.f32 %0, %1;" : "=f"(r) : "f"(x)); return r;
}
__device__ __forceinline__ float sigf(float v) {
    return fmaf(0.5f, tanha(0.5f * v), 0.5f);
}
__device__ __forceinline__ float lstm_out(float4 a, float &c) {
    float ig = sigf(a.x), fg = sigf(a.y);
    float gg = tanha(a.z), og = sigf(a.w);
    c = fg * c + ig * gg;
    return og * tanha(c);
}

// ---------------- gate accumulation: 2 rows x 4 gates per thread -------------
// ws: [k][rp(4)][rr(2)][gate(4)] floats = float4[k][8]
template <int K0, int K1>
__device__ __forceinline__ void accum2(const float4 *__restrict__ wsq,
                                       float4 &a0, float4 &a1,
                                       const float *__restrict__ in_s,
                                       int lane, int rp) {
    const float4 *wp = wsq + rp * 2;
    const float  *ip = in_s + lane;
#pragma unroll 4
    for (int k = K0; k < K1; k++) {
        float4 w0 = wp[k * 8];
        float4 w1 = wp[k * 8 + 1];
        float  v  = ip[k * 32];
        a0.x = fmaf(w0.x, v, a0.x); a0.y = fmaf(w0.y, v, a0.y);
        a0.z = fmaf(w0.z, v, a0.z); a0.w = fmaf(w0.w, v, a0.w);
        a1.x = fmaf(w1.x, v, a1.x); a1.y = fmaf(w1.y, v, a1.y);
        a1.z = fmaf(w1.z, v, a1.z); a1.w = fmaf(w1.w, v, a1.w);
    }
}

// combine 2 k-set partials: set1 (tid>=128) publishes, set0 sums.
__device__ __forceinline__ void combine2(float4 &a0, float4 &a1,
                                         float4 *psum, int tid, int set) {
    if (set == 1) {
        psum[(tid - 128) * 2]     = a0;
        psum[(tid - 128) * 2 + 1] = a1;
    }
    __syncthreads();
    if (set == 0) {
        float4 b0 = psum[tid * 2], b1 = psum[tid * 2 + 1];
        a0.x += b0.x; a0.y += b0.y; a0.z += b0.z; a0.w += b0.w;
        a1.x += b1.x; a1.y += b1.y; a1.z += b1.z; a1.w += b1.w;
    }
}

// stage one h vector (32 cols, 128 rows) L2 -> smem slot, 256 threads
__device__ __forceinline__ void stage_h(const float *__restrict__ src,
                                        float *__restrict__ dst, int tid) {
    const float4 *s4 = (const float4 *)src;
    float4 *d4 = (float4 *)dst;
#pragma unroll
    for (int i = 0; i < 4; i++) {
        int idx = tid + i * NTHR;          // 0..1023
        int row = idx >> 3, q = idx & 7;
        d4[row * 8 + q] = __ldcg(s4 + row * 64 + q);
    }
}

// ---------------- smem sizing (floats) ---------------------------------------
#define SMA_F (129*32 + 257*32 + 64 + 257*32 + 1024 + 32)
#define SMB_F (385*32 + 32 + 392 + 385*32 + 256 + 32 + 1024 + 32)
#define SMEM_F (SMB_F > SMA_F ? SMB_F : SMA_F)
#define SMEM_BYTES (SMEM_F * 4)

__global__ void __launch_bounds__(NTHR, 2)
lstm_pipe_kernel(const float *__restrict__ x,
                 const float *__restrict__ Wi1, const float *__restrict__ Wh1,
                 const float *__restrict__ bi1, const float *__restrict__ bh1,
                 const float *__restrict__ Wi2, const float *__restrict__ Wh2,
                 const float *__restrict__ bi2, const float *__restrict__ bh2,
                 const float *__restrict__ Wi3, const float *__restrict__ Wh3,
                 const float *__restrict__ bi3, const float *__restrict__ bh3,
                 const float *__restrict__ Wl,  const float *__restrict__ bl,
                 float *__restrict__ out, int T, int NT) {
    extern __shared__ float sm[];
    const int tid  = threadIdx.x;
    const int lane = tid & 31;
    const int wid  = tid >> 5;          // 0..7
    const int rp   = wid & 3;           // row-pair: rows 2rp, 2rp+1 (of 8)
    const int set  = wid >> 2;          // k-split set: 0,1
    const float4 zero4 = make_float4(0.f, 0.f, 0.f, 0.f);

    if (blockIdx.x < 128) {
        // =================== alpha : cell1 + cell2 ===========================
        const int hg = blockIdx.x >> 3, bg = blockIdx.x & 7;
        const int line = hg * 8 + bg;
        const int bcol = bg * 32 + lane;

        float *ws1f  = sm;
        float *ws2f  = ws1f + 129 * 32;
        float *biasf = ws2f + 257 * 32;
        float *big   = biasf + 64;
        float4 *psum = (float4 *)(big + 257 * 32);
        const float4 *ws1 = (const float4 *)ws1f;
        const float4 *ws2 = (const float4 *)ws2f;
        const float4 *bias4 = (const float4 *)biasf;

        for (int idx = tid; idx < 129 * 32; idx += NTHR) {
            int k = idx >> 5, t5 = idx & 31;
            int rpp = t5 >> 3, rr = (t5 >> 2) & 1, g = t5 & 3;
            int r = g * HH + hg * 8 + rpp * 2 + rr;
            ws1f[idx] = (k == 0) ? Wi1[r] : Wh1[r * HH + (k - 1)];
        }
        for (int idx = tid; idx < 257 * 32; idx += NTHR) {
            int k = idx >> 5, t5 = idx & 31;
            int rpp = t5 >> 3, rr = (t5 >> 2) & 1, g = t5 & 3;
            int r = g * HH + hg * 8 + rpp * 2 + rr;
            ws2f[idx] = (k < KK1) ? Wi2[r * KK1 + k] : Wh2[r * HH + (k - KK1)];
        }
        if (tid < 64) {
            int cell = tid >> 5, t5 = tid & 31;
            int rpp = t5 >> 3, rr = (t5 >> 2) & 1, g = t5 & 3;
            int r = g * HH + hg * 8 + rpp * 2 + rr;
            biasf[tid] = cell ? (bi2[r] + bh2[r]) : (bi1[r] + bh1[r]);
        }
        for (int idx = tid; idx < 257 * 32; idx += NTHR) big[idx] = 0.0f;
        __syncthreads();

        float c1a = 0.f, c1b = 0.f, c2a = 0.f, c2b = 0.f;
        const int gr0 = (hg * 8 + rp * 2) * BB + bcol;
        float xr = 0.f;
        if (tid < 32) xr = __ldg(&x[(bg * 32 + tid) * T]);

        for (int t = 0; t < NT; t++) {
            // backpressure: same-bg betas consumed h1/h2(t-2)
            flag_wait16(256, bg, t - 1, tid);
            if (t >= T) {
                flag_wait1(384 + bg, t, tid);
                if (tid < 32) big[tid] = __ldcg(&g_ox[bg * 32 + tid]);
            } else {
                if (tid < 32) big[tid] = xr;
            }
            __syncthreads();

            // ---- cell 1 (x + h1_prev slots, persistent) ---------------------
            float4 a0, a1;
            if (set == 0) {
                a0 = bias4[rp * 2]; a1 = bias4[rp * 2 + 1];
                accum2<0, 65>(ws1, a0, a1, big, lane, rp);
            } else {
                a0 = zero4; a1 = zero4;
                accum2<65, 129>(ws1, a0, a1, big, lane, rp);
            }
            combine2(a0, a1, psum, tid, set);
            if (set == 0) {
                g_h1[t & 1][gr0]      = lstm_out(a0, c1a);
                g_h1[t & 1][gr0 + BB] = lstm_out(a1, c1b);
            }
            __syncthreads();
            flag_set(line, 2 * t + 1, tid);

            if (tid < 32 && t + 1 < T) xr = __ldg(&x[(bg * 32 + tid) * T + t + 1]);

            // stage h2(t-1) (peers' flag 2t already set; wait ~free)
            flag_wait16(0, bg, 2 * t, tid);
            if (t > 0) stage_h(&g_h2[(t - 1) & 1][bg * 32], big + 129 * 32, tid);
            __syncthreads();

            // ---- cell2 partial: x (k=0) + h2_prev (129..257) ----------------
            float4 b0, b1;
            if (set == 0) {
                b0 = bias4[8 + rp * 2]; b1 = bias4[8 + rp * 2 + 1];
                accum2<0, 1>(ws2, b0, b1, big, lane, rp);
                accum2<129, 193>(ws2, b0, b1, big, lane, rp);
            } else {
                b0 = zero4; b1 = zero4;
                accum2<193, 257>(ws2, b0, b1, big, lane, rp);
            }

            flag_wait16(0, bg, 2 * t + 1, tid);        // h1(t) from same-bg peers
            stage_h(&g_h1[t & 1][bg * 32], big + 32, tid);
            __syncthreads();

            // ---- cell 2 finish over h1_new ----------------------------------
            if (set == 0) accum2<1, 65>(ws2, b0, b1, big, lane, rp);
            else          accum2<65, 129>(ws2, b0, b1, big, lane, rp);
            combine2(b0, b1, psum, tid, set);
            if (set == 0) {
                g_h2[t & 1][gr0]      = lstm_out(b0, c2a);
                g_h2[t & 1][gr0 + BB] = lstm_out(b1, c2b);
            }
            __syncthreads();
            flag_set(line, 2 * t + 2, tid);
        }
    } else {
        // =================== beta : cell3 + head =============================
        const int bidx = blockIdx.x - 128;
        const int hg = bidx >> 3, bg = bidx & 7;
        const int bcol = bg * 32 + lane;
        const int sub = wid;

        float *ws3f  = sm;
        float *biasf = ws3f + 385 * 32;
        float *wl    = biasf + 32;
        float *big   = wl + 392;
        float *po_s  = big + 385 * 32;
        float *ox    = po_s + 256;
        float4 *psum = (float4 *)(ox + 32);
        const float4 *ws3 = (const float4 *)ws3f;
        const float4 *bias4 = (const float4 *)biasf;

        for (int idx = tid; idx < 385 * 32; idx += NTHR) {
            int k = idx >> 5, t5 = idx & 31;
            int rpp = t5 >> 3, rr = (t5 >> 2) & 1, g = t5 & 3;
            int r = g * HH + hg * 8 + rpp * 2 + rr;
            ws3f[idx] = (k < 257) ? Wi3[r * 257 + k] : Wh3[r * HH + (k - 257)];
        }
        if (tid < 32) {
            int t5 = tid;
            int rpp = t5 >> 3, rr = (t5 >> 2) & 1, g = t5 & 3;
            int r = g * HH + hg * 8 + rpp * 2 + rr;
            biasf[tid] = bi3[r] + bh3[r];
        }
        for (int idx = tid; idx < 385; idx += NTHR) wl[idx] = Wl[idx];
        if (tid == 0) wl[385] = bl[0];
        if (tid < 32) ox[tid] = 0.0f;
        for (int idx = tid; idx < 385 * 32; idx += NTHR) big[idx] = 0.0f;
        __syncthreads();

        float c3a = 0.f, c3b = 0.f;
        const int gr0 = (hg * 8 + rp * 2) * BB + bcol;
        float xr = 0.f;
        if (tid < 32) xr = __ldg(&x[(bg * 32 + tid) * T]);

        for (int t = 0; t < NT; t++) {
            if (tid < 32) big[tid] = (t < T) ? xr : ox[tid];
            __syncthreads();

            // ---- cell3 partial: x (k=0) + h3_prev (257..385, persistent) ----
            float4 d0, d1;
            if (set == 0) {
                d0 = bias4[rp * 2]; d1 = bias4[rp * 2 + 1];
                accum2<0, 1>(ws3, d0, d1, big, lane, rp);
                accum2<257, 321>(ws3, d0, d1, big, lane, rp);
            } else {
                d0 = zero4; d1 = zero4;
                accum2<321, 385>(ws3, d0, d1, big, lane, rp);
            }

            flag_wait16(0, bg, 2 * t + 2, tid);        // alpha step t done
            stage_h(&g_h1[t & 1][bg * 32], big + 32, tid);
            stage_h(&g_h2[t & 1][bg * 32], big + 129 * 32, tid);
            __syncthreads();
            flag_set(256 + hg * 8 + bg, t + 1, tid);   // consumed

            if (tid < 32 && t + 1 < T) xr = __ldg(&x[(bg * 32 + tid) * T + t + 1]);

            // ---- cell 3 finish over h1,h2 -----------------------------------
            if (set == 0) accum2<1, 129>(ws3, d0, d1, big, lane, rp);
            else          accum2<129, 257>(ws3, d0, d1, big, lane, rp);
            combine2(d0, d1, psum, tid, set);
            if (set == 0) {
                g_h3[t & 1][gr0]      = lstm_out(d0, c3a);
                g_h3[t & 1][gr0 + BB] = lstm_out(d1, c3b);
            }
            __syncthreads();
            flag_set(128 + hg * 8 + bg, t + 1, tid);   // intra-beta arrive

            // head partial over x,h1,h2 while peers store h3
            float hp = 0.0f;
            for (int k = sub; k < 257; k += 8)
                hp = fmaf(wl[k], big[k * 32 + lane], hp);

            flag_wait16(128, bg, t + 1, tid);
            stage_h(&g_h3[t & 1][bg * 32], big + 257 * 32, tid);  // persists to t+1
            __syncthreads();

            for (int k = 257 + sub; k < 385; k += 8)
                hp = fmaf(wl[k], big[k * 32 + lane], hp);
            po_s[sub * 32 + lane] = hp;
            __syncthreads();
            if (tid < 32) {
                float o = wl[385];
#pragma unroll
                for (int s = 0; s < 8; s++) o += po_s[s * 32 + tid];
                ox[tid] = o;
                if (hg == 0) {
                    out[(bg * 32 + tid) * NT + t] = o;
                    g_ox[bg * 32 + tid] = o;
                }
            }
            __syncthreads();
            if (hg == 0) flag_set(384 + bg, t + 1, tid);
        }
    }
}

extern "C" void kernel_launch(void* const* d_in, const int* in_sizes, int n_in,
                              void* d_out, int out_size) {
    const float *x   = (const float *)d_in[0];
    const float *Wi1 = (const float *)d_in[1];
    const float *Wh1 = (const float *)d_in[2];
    const float *bi1 = (const float *)d_in[3];
    const float *bh1 = (const float *)d_in[4];
    const float *Wi2 = (const float *)d_in[5];
    const float *Wh2 = (const float *)d_in[6];
    const float *bi2 = (const float *)d_in[7];
    const float *bh2 = (const float *)d_in[8];
    const float *Wi3 = (const float *)d_in[9];
    const float *Wh3 = (const float *)d_in[10];
    const float *bi3 = (const float *)d_in[11];
    const float *bh3 = (const float *)d_in[12];
    const float *Wl  = (const float *)d_in[13];
    const float *bl  = (const float *)d_in[14];
    float *out = (float *)d_out;

    int T  = in_sizes[0] / BB;   // 1024
    int NT = out_size / BB;      // 1056

    cudaFuncSetAttribute(lstm_pipe_kernel,
                         cudaFuncAttributeMaxDynamicSharedMemorySize, SMEM_BYTES);

    lstm_bar_init<<<1, 256>>>();
    lstm_pipe_kernel<<<256, NTHR, SMEM_BYTES>>>(
        x, Wi1, Wh1, bi1, bh1, Wi2, Wh2, bi2, bh2,
        Wi3, Wh3, bi3, bh3, Wl, bl, out, T, NT);
}